// round 11
// baseline (speedup 1.0000x reference)
#include <cuda_runtime.h>
#include <cuda_bf16.h>
#include <cstdint>

#define Bn 8
#define Cc 256
#define Ci 128
#define Nn 4096   // 64*64
#define Mm 1024   // 32*32

// ---------------- scratch (static device allocations; no cudaMalloc) ------
__device__ __nv_bfloat16 d_wh  [4 * 32768];             // weight splits (theta,phi,g,w)
__device__ __nv_bfloat16 d_wl  [4 * 32768];
__device__ __nv_bfloat16 d_th_h[(size_t)Bn * Nn * Ci];  // theta hi [b][n][ci]
__device__ __nv_bfloat16 d_th_l[(size_t)Bn * Nn * Ci];
__device__ __nv_bfloat16 d_k_h [(size_t)Bn * Mm * Ci];  // K hi [b][m][ci]
__device__ __nv_bfloat16 d_k_l [(size_t)Bn * Mm * Ci];
__device__ __nv_bfloat16 d_v_h [(size_t)Bn * Mm * Ci];  // V hi [b][m][ci]
__device__ __nv_bfloat16 d_v_l [(size_t)Bn * Mm * Ci];
__device__ __nv_bfloat16 d_o_h [(size_t)Bn * Nn * Ci];  // attn out hi [b][n][ci]
__device__ __nv_bfloat16 d_o_l [(size_t)Bn * Nn * Ci];
__device__ float d_wy   [(size_t)Bn * Cc * Nn];         // [b][c][n]
__device__ float d_bnacc[2 * Cc];                       // BN partial sums (sum | sumsq)
__device__ float d_stats[2 * Cc];                       // mean, rstd

__device__ __forceinline__ uint32_t smem_u32(const void* p) {
    uint32_t a;
    asm("{ .reg .u64 t; cvta.to.shared.u64 t, %1; cvt.u32.u64 %0, t; }" : "=r"(a) : "l"(p));
    return a;
}
__device__ __forceinline__ uint32_t pack_bf16x2(float lo, float hi) {
    __nv_bfloat16 a = __float2bfloat16(lo), b = __float2bfloat16(hi);
    return (uint32_t)__bfloat16_as_ushort(a) | ((uint32_t)__bfloat16_as_ushort(b) << 16);
}
__device__ __forceinline__ void split_bf16(float v, __nv_bfloat16& h, __nv_bfloat16& l) {
    h = __float2bfloat16(v);
    l = __float2bfloat16(v - __bfloat162float(h));
}

#define LDSM4(r0, r1, r2, r3, addr) \
    asm volatile("ldmatrix.sync.aligned.m8n8.x4.shared.b16 {%0,%1,%2,%3}, [%4];" \
        : "=r"(r0), "=r"(r1), "=r"(r2), "=r"(r3) : "r"(addr))
#define LDSM4T(r0, r1, r2, r3, addr) \
    asm volatile("ldmatrix.sync.aligned.m8n8.x4.trans.shared.b16 {%0,%1,%2,%3}, [%4];" \
        : "=r"(r0), "=r"(r1), "=r"(r2), "=r"(r3) : "r"(addr))

#define MMA16816(C, A, b0, b1) \
    asm volatile("mma.sync.aligned.m16n8k16.row.col.f32.bf16.bf16.f32 " \
        "{%0,%1,%2,%3}, {%4,%5,%6,%7}, {%8,%9}, {%0,%1,%2,%3};" \
        : "+f"((C)[0]), "+f"((C)[1]), "+f"((C)[2]), "+f"((C)[3]) \
        : "r"((A)[0]), "r"((A)[1]), "r"((A)[2]), "r"((A)[3]), "r"(b0), "r"(b1))

#define CPA16(dst, src) \
    asm volatile("cp.async.cg.shared.global [%0], [%1], 16;" :: "r"(dst), "l"(src))
#define CPC() asm volatile("cp.async.commit_group;" ::: "memory")
#define CPW0() asm volatile("cp.async.wait_group 0;" ::: "memory")
#define CPW1() asm volatile("cp.async.wait_group 1;" ::: "memory")

// ---------------------------------------------------------------------------
// split all 4 weight matrices into bf16 hi/lo (elementwise)
// ---------------------------------------------------------------------------
__global__ void split_w_kernel(const float* __restrict__ tw, const float* __restrict__ pw,
                               const float* __restrict__ gw, const float* __restrict__ ww)
{
    int idx = blockIdx.x * blockDim.x + threadIdx.x;
    int seg = idx >> 15, off = idx & 32767;
    const float* src = (seg == 0) ? tw : (seg == 1) ? pw : (seg == 2) ? gw : ww;
    float v = src[off];
    __nv_bfloat16 h, l;
    split_bf16(v, h, l);
    d_wh[idx] = h; d_wl[idx] = l;
}

// ---------------------------------------------------------------------------
// tensor-core conv1x1, reads fp32 X [b][c][n] directly (no pre-transpose).
// ---------------------------------------------------------------------------
#define APITCH 132
#define CSTG 37376
#define CONV_SMEM 74752

__global__ __launch_bounds__(256, 2)
void conv_mma_kernel(const float* __restrict__ X,
                     const __nv_bfloat16* __restrict__ w_h, const __nv_bfloat16* __restrict__ w_l,
                     const float* __restrict__ bias,
                     __nv_bfloat16* __restrict__ out_h, __nv_bfloat16* __restrict__ out_l,
                     int pooled)
{
    extern __shared__ char dsm[];
    const uint32_t sb = smem_u32(dsm);

    const int b = blockIdx.y, n0 = blockIdx.x << 7;
    const int tid = threadIdx.x, w = tid >> 5, l = tid & 31;
    const int g = l >> 2, tig2 = (l & 3) * 2;

    const float* Ain = X + (size_t)b * Cc * Nn + n0;

    const uint32_t lmoff = (uint32_t)((((l & 7) | ((l >> 4) << 3)) * 80) + ((l >> 3) & 1) * 16);

    {
        uint32_t st = sb;
#pragma unroll
        for (int p = 0; p < 4; p++) {
            int f = tid + (p << 8);
            int row = f >> 5, seg = f & 31;
            CPA16(st + (uint32_t)(row * 528 + seg * 16), Ain + (size_t)row * Nn + seg * 4);
        }
#pragma unroll
        for (int p = 0; p < 4; p++) {
            int f = tid + (p << 8);
            int buf = f >> 9, idx = f & 511;
            int row = idx >> 2, seg = idx & 3;
            const __nv_bfloat16* src = (buf ? w_l : w_h) + (size_t)row * Cc + seg * 8;
            CPA16(st + (uint32_t)(16896 + buf * 10240 + row * 80 + seg * 16), src);
        }
        CPC();
    }

    float acc[64];
#pragma unroll
    for (int i = 0; i < 64; i++) acc[i] = 0.f;

    for (int c = 0; c < 8; c++) {
        if (c < 7) {
            const int k0 = (c + 1) * 32;
            uint32_t st = sb + ((c + 1) & 1) * CSTG;
#pragma unroll
            for (int p = 0; p < 4; p++) {
                int f = tid + (p << 8);
                int row = f >> 5, seg = f & 31;
                CPA16(st + (uint32_t)(row * 528 + seg * 16), Ain + (size_t)(k0 + row) * Nn + seg * 4);
            }
#pragma unroll
            for (int p = 0; p < 4; p++) {
                int f = tid + (p << 8);
                int buf = f >> 9, idx = f & 511;
                int row = idx >> 2, seg = idx & 3;
                const __nv_bfloat16* src = (buf ? w_l : w_h) + (size_t)row * Cc + k0 + seg * 8;
                CPA16(st + (uint32_t)(16896 + buf * 10240 + row * 80 + seg * 16), src);
            }
            CPC();
            CPW1();
        } else {
            CPW0();
        }
        __syncthreads();

        const float* As = (const float*)(dsm + (c & 1) * CSTG);
        const uint32_t st = sb + (c & 1) * CSTG;
        const uint32_t sBh = st + 16896, sBl = st + 27136;

#pragma unroll
        for (int kc = 0; kc < 2; kc++) {
            uint32_t aH[4], aL[4];
            const int kb = kc * 16 + tig2;
#pragma unroll
            for (int p = 0; p < 4; p++) {
                int k = kb + (p >> 1) * 8;
                int n = w * 16 + g + (p & 1) * 8;
                float v0 = As[k * APITCH + n];
                float v1 = As[(k + 1) * APITCH + n];
                __nv_bfloat16 h0, l0, h1, l1;
                split_bf16(v0, h0, l0); split_bf16(v1, h1, l1);
                aH[p] = (uint32_t)__bfloat16_as_ushort(h0) | ((uint32_t)__bfloat16_as_ushort(h1) << 16);
                aL[p] = (uint32_t)__bfloat16_as_ushort(l0) | ((uint32_t)__bfloat16_as_ushort(l1) << 16);
            }
#pragma unroll
            for (int np = 0; np < 8; np++) {
                uint32_t bbase = np * 16 * 80 + lmoff + kc * 32;
                uint32_t h0, h1, h2, h3, e0, e1, e2, e3;
                LDSM4(h0, h1, h2, h3, sBh + bbase);
                LDSM4(e0, e1, e2, e3, sBl + bbase);
                MMA16816(acc + (np * 2 + 0) * 4, aH, h0, h1);
                MMA16816(acc + (np * 2 + 0) * 4, aL, h0, h1);
                MMA16816(acc + (np * 2 + 0) * 4, aH, e0, e1);
                MMA16816(acc + (np * 2 + 1) * 4, aH, h2, h3);
                MMA16816(acc + (np * 2 + 1) * 4, aL, h2, h3);
                MMA16816(acc + (np * 2 + 1) * 4, aH, e2, e3);
            }
        }
        __syncthreads();
    }

    if (!pooled) {
        const int r0 = n0 + w * 16 + g;
#pragma unroll
        for (int j = 0; j < 16; j++) {
            int cb = (j >> 1) * 16 + (j & 1) * 8 + tig2;
            float b0 = __ldg(&bias[cb]), b1 = __ldg(&bias[cb + 1]);
            float v0 = acc[j * 4 + 0] + b0, v1 = acc[j * 4 + 1] + b1;
            float v2 = acc[j * 4 + 2] + b0, v3 = acc[j * 4 + 3] + b1;
            size_t p0 = ((size_t)b * Nn + r0) * Ci + cb;
            size_t p1 = p0 + 8 * Ci;
            __nv_bfloat16 h0, l0, h1, l1;
            split_bf16(v0, h0, l0); split_bf16(v1, h1, l1);
            *(uint32_t*)&out_h[p0] = (uint32_t)__bfloat16_as_ushort(h0) | ((uint32_t)__bfloat16_as_ushort(h1) << 16);
            *(uint32_t*)&out_l[p0] = (uint32_t)__bfloat16_as_ushort(l0) | ((uint32_t)__bfloat16_as_ushort(l1) << 16);
            split_bf16(v2, h0, l0); split_bf16(v3, h1, l1);
            *(uint32_t*)&out_h[p1] = (uint32_t)__bfloat16_as_ushort(h0) | ((uint32_t)__bfloat16_as_ushort(h1) << 16);
            *(uint32_t*)&out_l[p1] = (uint32_t)__bfloat16_as_ushort(l0) | ((uint32_t)__bfloat16_as_ushort(l1) << 16);
        }
    } else {
        float* pb = (float*)dsm;   // [128][132]
        const int r0 = w * 16 + g;
#pragma unroll
        for (int j = 0; j < 16; j++) {
            int cb = (j >> 1) * 16 + (j & 1) * 8 + tig2;
            float b0 = __ldg(&bias[cb]), b1 = __ldg(&bias[cb + 1]);
            pb[r0 * 132 + cb]           = acc[j * 4 + 0] + b0;
            pb[r0 * 132 + cb + 1]       = acc[j * 4 + 1] + b1;
            pb[(r0 + 8) * 132 + cb]     = acc[j * 4 + 2] + b0;
            pb[(r0 + 8) * 132 + cb + 1] = acc[j * 4 + 3] + b1;
        }
        __syncthreads();
        const int m0 = blockIdx.x << 5;
#pragma unroll
        for (int rep = 0; rep < 16; rep++) {
            int idx = tid + rep * 256;
            int pj = idx >> 7, ci = idx & 127;
            int rA = pj * 2;
            float v = fmaxf(fmaxf(pb[rA * 132 + ci],        pb[(rA + 1) * 132 + ci]),
                            fmaxf(pb[(rA + 64) * 132 + ci], pb[(rA + 65) * 132 + ci]));
            __nv_bfloat16 h, lo;
            split_bf16(v, h, lo);
            size_t o = ((size_t)b * Mm + m0 + pj) * Ci + ci;
            out_h[o] = h; out_l[o] = lo;
        }
    }
}

// ---------------------------------------------------------------------------
// mma.sync attention. Q fragments live in smem (ldmatrix per kc) -> ~56 fewer
// registers per thread. CTA: 8 warps x 16 query rows; 8 key tiles of 128.
// smem: K h/l + V h/l + Q h/l tiles, 6 x 34816 = 208896 B, 1 CTA/SM.
// ---------------------------------------------------------------------------
#define TPAD 272
#define TILE_BYTES (128 * TPAD)            // 34816
#define ATT_SMEM (6 * TILE_BYTES)          // 208896
#define EXP_SHIFT 40.0f

__device__ __forceinline__ void load_tile_async(uint32_t dst, const __nv_bfloat16* src)
{
    for (int f = threadIdx.x; f < 2048; f += 256) {
        int row = f >> 4, seg = f & 15;
        CPA16(dst + (uint32_t)(row * TPAD + seg * 16), src + (size_t)row * Ci + seg * 8);
    }
}

__global__ __launch_bounds__(256, 1) void attn_mma_kernel()
{
    extern __shared__ char smem[];
    const uint32_t sb = smem_u32(smem);
    const uint32_t sKh = sb, sKl = sb + TILE_BYTES;
    const uint32_t sVh = sb + 2 * TILE_BYTES, sVl = sb + 3 * TILE_BYTES;
    const uint32_t sQh = sb + 4 * TILE_BYTES, sQl = sb + 5 * TILE_BYTES;

    const int b = blockIdx.y, n0 = blockIdx.x << 7;
    const int tid = threadIdx.x, w = tid >> 5, l = tid & 31;
    const int g = l >> 2, tig2 = (l & 3) * 2;
    const int qr = n0 + w * 16 + g;

    const __nv_bfloat16* Kh = d_k_h + (size_t)b * Mm * Ci;
    const __nv_bfloat16* Kl = d_k_l + (size_t)b * Mm * Ci;
    const __nv_bfloat16* Vh = d_v_h + (size_t)b * Mm * Ci;
    const __nv_bfloat16* Vl = d_v_l + (size_t)b * Mm * Ci;

    // prologue: group0 = {K0, Q}, group1 = {V0}
    load_tile_async(sKh, Kh);
    load_tile_async(sKl, Kl);
    load_tile_async(sQh, d_th_h + ((size_t)b * Nn + n0) * Ci);
    load_tile_async(sQl, d_th_l + ((size_t)b * Nn + n0) * Ci);
    CPC();
    load_tile_async(sVh, Vh); load_tile_async(sVl, Vl); CPC();

    const uint32_t lmoff  = (uint32_t)(((l & 7) | ((l >> 4) << 3)) * TPAD + ((l >> 3) & 1) * 16);
    const uint32_t lmoffV = (uint32_t)(((l & 7) | (((l >> 3) & 1) << 3)) * TPAD + (l >> 4) * 16);
    const uint32_t qbase  = w * 16 * TPAD + lmoff;

    float S[64], O[64];
#pragma unroll
    for (int i = 0; i < 64; i++) O[i] = 0.f;
    float l_lo = 0.f, l_hi = 0.f;

    for (int it = 0; it < 8; it++) {
        CPW1();
        __syncthreads();

        // ---- S = Q K^T (bf16x3), kc-outer / np-inner; Q frags from smem ----
#pragma unroll
        for (int i = 0; i < 64; i++) S[i] = 0.f;
#pragma unroll
        for (int kc = 0; kc < 8; kc++) {
            uint32_t qH[4], qL[4];
            LDSM4(qH[0], qH[2], qH[1], qH[3], sQh + qbase + kc * 32);
            LDSM4(qL[0], qL[2], qL[1], qL[3], sQl + qbase + kc * 32);
            uint32_t kb  = sKh + lmoff + kc * 32;
            uint32_t kb2 = sKl + lmoff + kc * 32;
#pragma unroll
            for (int np = 0; np < 8; np++) {
                uint32_t h0, h1, h2, h3, e0, e1, e2, e3;
                LDSM4(h0, h1, h2, h3, kb + np * 16 * TPAD);
                LDSM4(e0, e1, e2, e3, kb2 + np * 16 * TPAD);
                MMA16816(S + np * 8,     qH, h0, h1);
                MMA16816(S + np * 8,     qL, h0, h1);
                MMA16816(S + np * 8,     qH, e0, e1);
                MMA16816(S + np * 8 + 4, qH, h2, h3);
                MMA16816(S + np * 8 + 4, qL, h2, h3);
                MMA16816(S + np * 8 + 4, qH, e2, e3);
            }
        }
        __syncthreads();

        // ---- softmax numerator: p = exp(s-40); pack P hi/lo in place ----
        uint32_t* P = (uint32_t*)S;
#pragma unroll
        for (int kc = 0; kc < 8; kc++) {
            float p[8];
#pragma unroll
            for (int i = 0; i < 8; i++) p[i] = __expf(S[kc * 8 + i] - EXP_SHIFT);
            l_lo += (p[0] + p[1]) + (p[4] + p[5]);
            l_hi += (p[2] + p[3]) + (p[6] + p[7]);
            float hf[8], lf[8];
#pragma unroll
            for (int i = 0; i < 8; i++) {
                __nv_bfloat16 h = __float2bfloat16(p[i]);
                hf[i] = __bfloat162float(h);
                lf[i] = p[i] - hf[i];
            }
            P[kc * 8 + 0] = pack_bf16x2(hf[0], hf[1]);
            P[kc * 8 + 1] = pack_bf16x2(hf[2], hf[3]);
            P[kc * 8 + 2] = pack_bf16x2(hf[4], hf[5]);
            P[kc * 8 + 3] = pack_bf16x2(hf[6], hf[7]);
            P[kc * 8 + 4] = pack_bf16x2(lf[0], lf[1]);
            P[kc * 8 + 5] = pack_bf16x2(lf[2], lf[3]);
            P[kc * 8 + 6] = pack_bf16x2(lf[4], lf[5]);
            P[kc * 8 + 7] = pack_bf16x2(lf[6], lf[7]);
        }

        CPW0();
        __syncthreads();

        if (it < 7) {
            load_tile_async(sKh, Kh + (size_t)(it + 1) * 128 * Ci);
            load_tile_async(sKl, Kl + (size_t)(it + 1) * 128 * Ci);
            CPC();
        }

        // ---- O += P V (bf16x3), V via ldmatrix.trans ----
#pragma unroll
        for (int kc = 0; kc < 8; kc++) {     // m chunks of 16
#pragma unroll
            for (int np = 0; np < 8; np++) { // ci chunks of 16
                uint32_t vb  = sVh + kc * 16 * TPAD + np * 32 + lmoffV;
                uint32_t vb2 = sVl + kc * 16 * TPAD + np * 32 + lmoffV;
                uint32_t h0, h1, h2, h3, e0, e1, e2, e3;
                LDSM4T(h0, h1, h2, h3, vb);
                LDSM4T(e0, e1, e2, e3, vb2);
                MMA16816(O + np * 8,     P + kc * 8,     h0, h1);
                MMA16816(O + np * 8,     P + kc * 8 + 4, h0, h1);
                MMA16816(O + np * 8,     P + kc * 8,     e0, e1);
                MMA16816(O + np * 8 + 4, P + kc * 8,     h2, h3);
                MMA16816(O + np * 8 + 4, P + kc * 8 + 4, h2, h3);
                MMA16816(O + np * 8 + 4, P + kc * 8,     e2, e3);
            }
        }
        __syncthreads();

        if (it < 7) {
            load_tile_async(sVh, Vh + (size_t)(it + 1) * 128 * Ci);
            load_tile_async(sVl, Vl + (size_t)(it + 1) * 128 * Ci);
            CPC();
        }
    }

    l_lo += __shfl_xor_sync(0xffffffffu, l_lo, 1);
    l_lo += __shfl_xor_sync(0xffffffffu, l_lo, 2);
    l_hi += __shfl_xor_sync(0xffffffffu, l_hi, 1);
    l_hi += __shfl_xor_sync(0xffffffffu, l_hi, 2);
    float i0 = 1.0f / l_lo, i1 = 1.0f / l_hi;

    size_t base0 = ((size_t)b * Nn + qr) * Ci;
    size_t base1 = base0 + 8 * Ci;
#pragma unroll
    for (int nb = 0; nb < 16; nb++) {
        float v0 = O[nb * 4 + 0] * i0, v1 = O[nb * 4 + 1] * i0;
        float v2 = O[nb * 4 + 2] * i1, v3 = O[nb * 4 + 3] * i1;
        __nv_bfloat16 h0, l0, h1, l1;
        split_bf16(v0, h0, l0); split_bf16(v1, h1, l1);
        *(uint32_t*)&d_o_h[base0 + nb * 8 + tig2] =
            (uint32_t)__bfloat16_as_ushort(h0) | ((uint32_t)__bfloat16_as_ushort(h1) << 16);
        *(uint32_t*)&d_o_l[base0 + nb * 8 + tig2] =
            (uint32_t)__bfloat16_as_ushort(l0) | ((uint32_t)__bfloat16_as_ushort(l1) << 16);
        split_bf16(v2, h0, l0); split_bf16(v3, h1, l1);
        *(uint32_t*)&d_o_h[base1 + nb * 8 + tig2] =
            (uint32_t)__bfloat16_as_ushort(h0) | ((uint32_t)__bfloat16_as_ushort(h1) << 16);
        *(uint32_t*)&d_o_l[base1 + nb * 8 + tig2] =
            (uint32_t)__bfloat16_as_ushort(l0) | ((uint32_t)__bfloat16_as_ushort(l1) << 16);
    }
}

// ---------------------------------------------------------------------------
// tensor-core W projection + fused BN stats, 2-stage cp.async pipelined.
// ---------------------------------------------------------------------------
#define WSTG 40960
#define WPROJ_SMEM 81920

__global__ __launch_bounds__(256, 2)
void wproj_mma_kernel(const __nv_bfloat16* __restrict__ w_h, const __nv_bfloat16* __restrict__ w_l,
                      const float* __restrict__ bias)
{
    extern __shared__ char dsm[];
    const uint32_t sb = smem_u32(dsm);

    const int b = blockIdx.z, cb0 = blockIdx.y << 7, n0 = blockIdx.x << 7;
    const int tid = threadIdx.x, w = tid >> 5, l = tid & 31;
    const int g = l >> 2, tig2 = (l & 3) * 2;

    const __nv_bfloat16* Bin_h = d_o_h + ((size_t)b * Nn + n0) * Ci;
    const __nv_bfloat16* Bin_l = d_o_l + ((size_t)b * Nn + n0) * Ci;

    const uint32_t lmoff = (uint32_t)((((l & 7) | ((l >> 4) << 3)) * 80) + ((l >> 3) & 1) * 16);

    {
        const int k0 = 0;
        uint32_t st = sb;
#pragma unroll
        for (int p = 0; p < 8; p++) {
            int f = tid + (p << 8);
            int buf = f >> 9, idx = f & 511;
            int row = idx >> 2, seg = idx & 3;
            const __nv_bfloat16* src =
                (buf == 0) ? w_h   + (size_t)(cb0 + row) * Ci + k0 + seg * 8 :
                (buf == 1) ? w_l   + (size_t)(cb0 + row) * Ci + k0 + seg * 8 :
                (buf == 2) ? Bin_h + (size_t)row * Ci + k0 + seg * 8 :
                             Bin_l + (size_t)row * Ci + k0 + seg * 8;
            CPA16(st + (uint32_t)(buf * 10240 + row * 80 + seg * 16), src);
        }
        CPC();
    }

    float acc[64];
#pragma unroll
    for (int i = 0; i < 64; i++) acc[i] = 0.f;

    for (int c = 0; c < 4; c++) {
        if (c < 3) {
            const int k0 = (c + 1) * 32;
            uint32_t st = sb + ((c + 1) & 1) * WSTG;
#pragma unroll
            for (int p = 0; p < 8; p++) {
                int f = tid + (p << 8);
                int buf = f >> 9, idx = f & 511;
                int row = idx >> 2, seg = idx & 3;
                const __nv_bfloat16* src =
                    (buf == 0) ? w_h   + (size_t)(cb0 + row) * Ci + k0 + seg * 8 :
                    (buf == 1) ? w_l   + (size_t)(cb0 + row) * Ci + k0 + seg * 8 :
                    (buf == 2) ? Bin_h + (size_t)row * Ci + k0 + seg * 8 :
                                 Bin_l + (size_t)row * Ci + k0 + seg * 8;
                CPA16(st + (uint32_t)(buf * 10240 + row * 80 + seg * 16), src);
            }
            CPC();
            CPW1();
        } else {
            CPW0();
        }
        __syncthreads();

        const uint32_t st = sb + (c & 1) * WSTG;
        const uint32_t sAh = st, sAl = st + 10240, sBh = st + 20480, sBl = st + 30720;

#pragma unroll
        for (int kc = 0; kc < 2; kc++) {
            uint32_t aH[4], aL[4];
            uint32_t abase = w * 16 * 80 + lmoff + kc * 32;
            LDSM4(aH[0], aH[2], aH[1], aH[3], sAh + abase);
            LDSM4(aL[0], aL[2], aL[1], aL[3], sAl + abase);
#pragma unroll
            for (int np = 0; np < 8; np++) {
                uint32_t bbase = np * 16 * 80 + lmoff + kc * 32;
                uint32_t h0, h1, h2, h3, e0, e1, e2, e3;
                LDSM4(h0, h1, h2, h3, sBh + bbase);
                LDSM4(e0, e1, e2, e3, sBl + bbase);
                MMA16816(acc + (np * 2 + 0) * 4, aH, h0, h1);
                MMA16816(acc + (np * 2 + 0) * 4, aL, h0, h1);
                MMA16816(acc + (np * 2 + 0) * 4, aH, e0, e1);
                MMA16816(acc + (np * 2 + 1) * 4, aH, h2, h3);
                MMA16816(acc + (np * 2 + 1) * 4, aL, h2, h3);
                MMA16816(acc + (np * 2 + 1) * 4, aH, e2, e3);
            }
        }
        __syncthreads();
    }

    const int c0 = cb0 + w * 16 + g;
    float bv0 = __ldg(&bias[c0]), bv1 = __ldg(&bias[c0 + 8]);
    float s0 = 0.f, q0 = 0.f, s1 = 0.f, q1 = 0.f;
#pragma unroll
    for (int j = 0; j < 16; j++) {
        int ncol = n0 + (j >> 1) * 16 + (j & 1) * 8 + tig2;
        float v0 = acc[j * 4 + 0] + bv0, v1 = acc[j * 4 + 1] + bv0;
        float v2 = acc[j * 4 + 2] + bv1, v3 = acc[j * 4 + 3] + bv1;
        s0 += v0 + v1; q0 += v0 * v0 + v1 * v1;
        s1 += v2 + v3; q1 += v2 * v2 + v3 * v3;
        *(float2*)&d_wy[((size_t)b * Cc + c0) * Nn + ncol]     = make_float2(v0, v1);
        *(float2*)&d_wy[((size_t)b * Cc + c0 + 8) * Nn + ncol] = make_float2(v2, v3);
    }
    s0 += __shfl_xor_sync(0xffffffffu, s0, 1); s0 += __shfl_xor_sync(0xffffffffu, s0, 2);
    q0 += __shfl_xor_sync(0xffffffffu, q0, 1); q0 += __shfl_xor_sync(0xffffffffu, q0, 2);
    s1 += __shfl_xor_sync(0xffffffffu, s1, 1); s1 += __shfl_xor_sync(0xffffffffu, s1, 2);
    q1 += __shfl_xor_sync(0xffffffffu, q1, 1); q1 += __shfl_xor_sync(0xffffffffu, q1, 2);
    if ((l & 3) == 0) {
        atomicAdd(&d_bnacc[c0], s0);          atomicAdd(&d_bnacc[Cc + c0], q0);
        atomicAdd(&d_bnacc[c0 + 8], s1);      atomicAdd(&d_bnacc[Cc + c0 + 8], q1);
    }
}

// -------------------------- BN stats finalize ------------------------------
__global__ void bn_stats_finalize()
{
    int c = threadIdx.x;
    float inv = 1.0f / (float)(Bn * Nn);
    float mean = d_bnacc[c] * inv;
    float var = fmaxf(d_bnacc[Cc + c] * inv - mean * mean, 0.f);
    d_stats[c] = mean;
    d_stats[Cc + c] = rsqrtf(var + 1e-5f);
}

// ----------------------- finalize: BN affine + residual --------------------
__global__ void finalize_kernel(const float* __restrict__ x,
                                const float* __restrict__ gamma,
                                const float* __restrict__ beta,
                                float* __restrict__ out)
{
    size_t i4 = (size_t)blockIdx.x * blockDim.x + threadIdx.x;
    size_t total4 = (size_t)Bn * Cc * Nn / 4;
    if (i4 >= total4) return;
    size_t i = i4 * 4;
    int c = (int)((i >> 12) & (Cc - 1));
    float mean = d_stats[c];
    float ga = __ldg(&gamma[c]) * d_stats[Cc + c];
    float be = __ldg(&beta[c]);
    float4 w  = *(const float4*)&d_wy[i];
    float4 xv = *(const float4*)&x[i];
    float4 o;
    o.x = (w.x - mean) * ga + be + xv.x;
    o.y = (w.y - mean) * ga + be + xv.y;
    o.z = (w.z - mean) * ga + be + xv.z;
    o.w = (w.w - mean) * ga + be + xv.w;
    *(float4*)&out[i] = o;
}

// ---------------------------------------------------------------------------
extern "C" void kernel_launch(void* const* d_in, const int* in_sizes, int n_in,
                              void* d_out, int out_size)
{
    const float* x       = (const float*)d_in[0];
    const float* y       = (const float*)d_in[1];
    const float* theta_w = (const float*)d_in[2];
    const float* theta_b = (const float*)d_in[3];
    const float* phi_w   = (const float*)d_in[4];
    const float* phi_b   = (const float*)d_in[5];
    const float* g_w     = (const float*)d_in[6];
    const float* g_b     = (const float*)d_in[7];
    const float* w_w     = (const float*)d_in[8];
    const float* w_b     = (const float*)d_in[9];
    const float* gamma   = (const float*)d_in[10];
    const float* beta    = (const float*)d_in[11];
    float* out = (float*)d_out;

    cudaFuncSetAttribute(attn_mma_kernel, cudaFuncAttributeMaxDynamicSharedMemorySize, ATT_SMEM);
    cudaFuncSetAttribute(conv_mma_kernel, cudaFuncAttributeMaxDynamicSharedMemorySize, CONV_SMEM);
    cudaFuncSetAttribute(wproj_mma_kernel, cudaFuncAttributeMaxDynamicSharedMemorySize, WPROJ_SMEM);

    __nv_bfloat16 *wh_p, *wl_p, *thh, *thl, *kh, *kl, *vh, *vl;
    float *bnacc_p;
    cudaGetSymbolAddress((void**)&wh_p, d_wh);
    cudaGetSymbolAddress((void**)&wl_p, d_wl);
    cudaGetSymbolAddress((void**)&thh, d_th_h);
    cudaGetSymbolAddress((void**)&thl, d_th_l);
    cudaGetSymbolAddress((void**)&kh,  d_k_h);
    cudaGetSymbolAddress((void**)&kl,  d_k_l);
    cudaGetSymbolAddress((void**)&vh,  d_v_h);
    cudaGetSymbolAddress((void**)&vl,  d_v_l);
    cudaGetSymbolAddress((void**)&bnacc_p, d_bnacc);

    // launch 0: single memset (keeps attention at profiled launch index 5)
    cudaMemsetAsync(bnacc_p, 0, 2 * Cc * sizeof(float));

    split_w_kernel<<<512, 256>>>(theta_w, phi_w, g_w, w_w);          // launch 1

    dim3 gConv(Nn / 128, Bn);
    conv_mma_kernel<<<gConv, 256, CONV_SMEM>>>(x, wh_p, wl_p, theta_b, thh, thl, 0);          // 2
    conv_mma_kernel<<<gConv, 256, CONV_SMEM>>>(y, wh_p + 32768, wl_p + 32768, phi_b, kh, kl, 1);       // 3
    conv_mma_kernel<<<gConv, 256, CONV_SMEM>>>(y, wh_p + 2 * 32768, wl_p + 2 * 32768, g_b, vh, vl, 1); // 4

    attn_mma_kernel<<<dim3(Nn / 128, Bn), 256, ATT_SMEM>>>();        // launch 5 (profiled)

    wproj_mma_kernel<<<dim3(Nn / 128, Cc / 128, Bn), 256, WPROJ_SMEM>>>(wh_p + 3 * 32768, wl_p + 3 * 32768, w_b);
    bn_stats_finalize<<<1, Cc>>>();
    finalize_kernel<<<(Bn * Cc * Nn / 4 + 255) / 256, 256>>>(x, gamma, beta, out);
}

// round 14
// speedup vs baseline: 1.0369x; 1.0369x over previous
#include <cuda_runtime.h>
#include <cuda_bf16.h>
#include <cstdint>

#define Bn 8
#define Cc 256
#define Ci 128
#define Nn 4096   // 64*64
#define Mm 1024   // 32*32

// ---------------- scratch (static device allocations; no cudaMalloc) ------
__device__ __nv_bfloat16 d_wh  [4 * 32768];             // weight splits (theta,phi,g,w)
__device__ __nv_bfloat16 d_wl  [4 * 32768];
__device__ __nv_bfloat16 d_th_h[(size_t)Bn * Nn * Ci];  // theta hi [b][n][ci]
__device__ __nv_bfloat16 d_th_l[(size_t)Bn * Nn * Ci];
__device__ __nv_bfloat16 d_k_h [(size_t)Bn * Mm * Ci];  // K hi [b][m][ci]
__device__ __nv_bfloat16 d_k_l [(size_t)Bn * Mm * Ci];
__device__ __nv_bfloat16 d_v_h [(size_t)Bn * Mm * Ci];  // V hi [b][m][ci]
__device__ __nv_bfloat16 d_v_l [(size_t)Bn * Mm * Ci];
__device__ __nv_bfloat16 d_o_h [(size_t)Bn * Nn * Ci];  // attn out hi [b][n][ci]
__device__ __nv_bfloat16 d_o_l [(size_t)Bn * Nn * Ci];
__device__ float d_wy   [(size_t)Bn * Cc * Nn];         // [b][c][n]
__device__ float d_bnacc[2 * Cc];                       // BN partial sums (sum | sumsq)

__device__ __forceinline__ uint32_t smem_u32(const void* p) {
    uint32_t a;
    asm("{ .reg .u64 t; cvta.to.shared.u64 t, %1; cvt.u32.u64 %0, t; }" : "=r"(a) : "l"(p));
    return a;
}
__device__ __forceinline__ uint32_t pack_bf16x2(float lo, float hi) {
    __nv_bfloat16 a = __float2bfloat16(lo), b = __float2bfloat16(hi);
    return (uint32_t)__bfloat16_as_ushort(a) | ((uint32_t)__bfloat16_as_ushort(b) << 16);
}
__device__ __forceinline__ void split_bf16(float v, __nv_bfloat16& h, __nv_bfloat16& l) {
    h = __float2bfloat16(v);
    l = __float2bfloat16(v - __bfloat162float(h));
}

#define LDSM4(r0, r1, r2, r3, addr) \
    asm volatile("ldmatrix.sync.aligned.m8n8.x4.shared.b16 {%0,%1,%2,%3}, [%4];" \
        : "=r"(r0), "=r"(r1), "=r"(r2), "=r"(r3) : "r"(addr))
#define LDSM4T(r0, r1, r2, r3, addr) \
    asm volatile("ldmatrix.sync.aligned.m8n8.x4.trans.shared.b16 {%0,%1,%2,%3}, [%4];" \
        : "=r"(r0), "=r"(r1), "=r"(r2), "=r"(r3) : "r"(addr))

#define MMA16816(C, A, b0, b1) \
    asm volatile("mma.sync.aligned.m16n8k16.row.col.f32.bf16.bf16.f32 " \
        "{%0,%1,%2,%3}, {%4,%5,%6,%7}, {%8,%9}, {%0,%1,%2,%3};" \
        : "+f"((C)[0]), "+f"((C)[1]), "+f"((C)[2]), "+f"((C)[3]) \
        : "r"((A)[0]), "r"((A)[1]), "r"((A)[2]), "r"((A)[3]), "r"(b0), "r"(b1))

#define CPA16(dst, src) \
    asm volatile("cp.async.cg.shared.global [%0], [%1], 16;" :: "r"(dst), "l"(src))
#define CPC() asm volatile("cp.async.commit_group;" ::: "memory")
#define CPW0() asm volatile("cp.async.wait_group 0;" ::: "memory")
#define CPW1() asm volatile("cp.async.wait_group 1;" ::: "memory")

// ---------------------------------------------------------------------------
// split all 4 weight matrices into bf16 hi/lo (elementwise)
// ---------------------------------------------------------------------------
__global__ void split_w_kernel(const float* __restrict__ tw, const float* __restrict__ pw,
                               const float* __restrict__ gw, const float* __restrict__ ww)
{
    int idx = blockIdx.x * blockDim.x + threadIdx.x;
    int seg = idx >> 15, off = idx & 32767;
    const float* src = (seg == 0) ? tw : (seg == 1) ? pw : (seg == 2) ? gw : ww;
    float v = src[off];
    __nv_bfloat16 h, l;
    split_bf16(v, h, l);
    d_wh[idx] = h; d_wl[idx] = l;
}

// ---------------------------------------------------------------------------
// tensor-core conv1x1, reads fp32 X [b][c][n] directly (no pre-transpose).
// ---------------------------------------------------------------------------
#define APITCH 132
#define CSTG 37376
#define CONV_SMEM 74752

__global__ __launch_bounds__(256, 2)
void conv_mma_kernel(const float* __restrict__ X,
                     const __nv_bfloat16* __restrict__ w_h, const __nv_bfloat16* __restrict__ w_l,
                     const float* __restrict__ bias,
                     __nv_bfloat16* __restrict__ out_h, __nv_bfloat16* __restrict__ out_l,
                     int pooled)
{
    extern __shared__ char dsm[];
    const uint32_t sb = smem_u32(dsm);

    const int b = blockIdx.y, n0 = blockIdx.x << 7;
    const int tid = threadIdx.x, w = tid >> 5, l = tid & 31;
    const int g = l >> 2, tig2 = (l & 3) * 2;

    const float* Ain = X + (size_t)b * Cc * Nn + n0;

    const uint32_t lmoff = (uint32_t)((((l & 7) | ((l >> 4) << 3)) * 80) + ((l >> 3) & 1) * 16);

    {
        uint32_t st = sb;
#pragma unroll
        for (int p = 0; p < 4; p++) {
            int f = tid + (p << 8);
            int row = f >> 5, seg = f & 31;
            CPA16(st + (uint32_t)(row * 528 + seg * 16), Ain + (size_t)row * Nn + seg * 4);
        }
#pragma unroll
        for (int p = 0; p < 4; p++) {
            int f = tid + (p << 8);
            int buf = f >> 9, idx = f & 511;
            int row = idx >> 2, seg = idx & 3;
            const __nv_bfloat16* src = (buf ? w_l : w_h) + (size_t)row * Cc + seg * 8;
            CPA16(st + (uint32_t)(16896 + buf * 10240 + row * 80 + seg * 16), src);
        }
        CPC();
    }

    float acc[64];
#pragma unroll
    for (int i = 0; i < 64; i++) acc[i] = 0.f;

    for (int c = 0; c < 8; c++) {
        if (c < 7) {
            const int k0 = (c + 1) * 32;
            uint32_t st = sb + ((c + 1) & 1) * CSTG;
#pragma unroll
            for (int p = 0; p < 4; p++) {
                int f = tid + (p << 8);
                int row = f >> 5, seg = f & 31;
                CPA16(st + (uint32_t)(row * 528 + seg * 16), Ain + (size_t)(k0 + row) * Nn + seg * 4);
            }
#pragma unroll
            for (int p = 0; p < 4; p++) {
                int f = tid + (p << 8);
                int buf = f >> 9, idx = f & 511;
                int row = idx >> 2, seg = idx & 3;
                const __nv_bfloat16* src = (buf ? w_l : w_h) + (size_t)row * Cc + k0 + seg * 8;
                CPA16(st + (uint32_t)(16896 + buf * 10240 + row * 80 + seg * 16), src);
            }
            CPC();
            CPW1();
        } else {
            CPW0();
        }
        __syncthreads();

        const float* As = (const float*)(dsm + (c & 1) * CSTG);
        const uint32_t st = sb + (c & 1) * CSTG;
        const uint32_t sBh = st + 16896, sBl = st + 27136;

#pragma unroll
        for (int kc = 0; kc < 2; kc++) {
            uint32_t aH[4], aL[4];
            const int kb = kc * 16 + tig2;
#pragma unroll
            for (int p = 0; p < 4; p++) {
                int k = kb + (p >> 1) * 8;
                int n = w * 16 + g + (p & 1) * 8;
                float v0 = As[k * APITCH + n];
                float v1 = As[(k + 1) * APITCH + n];
                __nv_bfloat16 h0, l0, h1, l1;
                split_bf16(v0, h0, l0); split_bf16(v1, h1, l1);
                aH[p] = (uint32_t)__bfloat16_as_ushort(h0) | ((uint32_t)__bfloat16_as_ushort(h1) << 16);
                aL[p] = (uint32_t)__bfloat16_as_ushort(l0) | ((uint32_t)__bfloat16_as_ushort(l1) << 16);
            }
#pragma unroll
            for (int np = 0; np < 8; np++) {
                uint32_t bbase = np * 16 * 80 + lmoff + kc * 32;
                uint32_t h0, h1, h2, h3, e0, e1, e2, e3;
                LDSM4(h0, h1, h2, h3, sBh + bbase);
                LDSM4(e0, e1, e2, e3, sBl + bbase);
                MMA16816(acc + (np * 2 + 0) * 4, aH, h0, h1);
                MMA16816(acc + (np * 2 + 0) * 4, aL, h0, h1);
                MMA16816(acc + (np * 2 + 0) * 4, aH, e0, e1);
                MMA16816(acc + (np * 2 + 1) * 4, aH, h2, h3);
                MMA16816(acc + (np * 2 + 1) * 4, aL, h2, h3);
                MMA16816(acc + (np * 2 + 1) * 4, aH, e2, e3);
            }
        }
        __syncthreads();
    }

    if (!pooled) {
        const int r0 = n0 + w * 16 + g;
#pragma unroll
        for (int j = 0; j < 16; j++) {
            int cb = (j >> 1) * 16 + (j & 1) * 8 + tig2;
            float b0 = __ldg(&bias[cb]), b1 = __ldg(&bias[cb + 1]);
            float v0 = acc[j * 4 + 0] + b0, v1 = acc[j * 4 + 1] + b1;
            float v2 = acc[j * 4 + 2] + b0, v3 = acc[j * 4 + 3] + b1;
            size_t p0 = ((size_t)b * Nn + r0) * Ci + cb;
            size_t p1 = p0 + 8 * Ci;
            __nv_bfloat16 h0, l0, h1, l1;
            split_bf16(v0, h0, l0); split_bf16(v1, h1, l1);
            *(uint32_t*)&out_h[p0] = (uint32_t)__bfloat16_as_ushort(h0) | ((uint32_t)__bfloat16_as_ushort(h1) << 16);
            *(uint32_t*)&out_l[p0] = (uint32_t)__bfloat16_as_ushort(l0) | ((uint32_t)__bfloat16_as_ushort(l1) << 16);
            split_bf16(v2, h0, l0); split_bf16(v3, h1, l1);
            *(uint32_t*)&out_h[p1] = (uint32_t)__bfloat16_as_ushort(h0) | ((uint32_t)__bfloat16_as_ushort(h1) << 16);
            *(uint32_t*)&out_l[p1] = (uint32_t)__bfloat16_as_ushort(l0) | ((uint32_t)__bfloat16_as_ushort(l1) << 16);
        }
    } else {
        float* pb = (float*)dsm;   // [128][132]
        const int r0 = w * 16 + g;
#pragma unroll
        for (int j = 0; j < 16; j++) {
            int cb = (j >> 1) * 16 + (j & 1) * 8 + tig2;
            float b0 = __ldg(&bias[cb]), b1 = __ldg(&bias[cb + 1]);
            pb[r0 * 132 + cb]           = acc[j * 4 + 0] + b0;
            pb[r0 * 132 + cb + 1]       = acc[j * 4 + 1] + b1;
            pb[(r0 + 8) * 132 + cb]     = acc[j * 4 + 2] + b0;
            pb[(r0 + 8) * 132 + cb + 1] = acc[j * 4 + 3] + b1;
        }
        __syncthreads();
        const int m0 = blockIdx.x << 5;
#pragma unroll
        for (int rep = 0; rep < 16; rep++) {
            int idx = tid + rep * 256;
            int pj = idx >> 7, ci = idx & 127;
            int rA = pj * 2;
            float v = fmaxf(fmaxf(pb[rA * 132 + ci],        pb[(rA + 1) * 132 + ci]),
                            fmaxf(pb[(rA + 64) * 132 + ci], pb[(rA + 65) * 132 + ci]));
            __nv_bfloat16 h, lo;
            split_bf16(v, h, lo);
            size_t o = ((size_t)b * Mm + m0 + pj) * Ci + ci;
            out_h[o] = h; out_l[o] = lo;
        }
    }
}

// ---------------------------------------------------------------------------
// mma.sync attention (R9 config — best at 298.7us): softmax fused per key
// chunk, Q in registers. CTA: 8 warps x 16 query rows; 8 key tiles of 128.
// ---------------------------------------------------------------------------
#define TPAD 272
#define TILE_BYTES (128 * TPAD)            // 34816
#define ATT_SMEM (4 * TILE_BYTES)          // 139264
#define EXP_SHIFT 40.0f

__device__ __forceinline__ void load_tile_async(uint32_t dst, const __nv_bfloat16* src)
{
    for (int f = threadIdx.x; f < 2048; f += 256) {
        int row = f >> 4, seg = f & 15;
        CPA16(dst + (uint32_t)(row * TPAD + seg * 16), src + (size_t)row * Ci + seg * 8);
    }
}

__global__ __launch_bounds__(256, 1) void attn_mma_kernel()
{
    extern __shared__ char smem[];
    const uint32_t sb = smem_u32(smem);
    const uint32_t sKh = sb, sKl = sb + TILE_BYTES;
    const uint32_t sVh = sb + 2 * TILE_BYTES, sVl = sb + 3 * TILE_BYTES;

    const int b = blockIdx.y, n0 = blockIdx.x << 7;
    const int tid = threadIdx.x, w = tid >> 5, l = tid & 31;
    const int g = l >> 2, tig2 = (l & 3) * 2;
    const int qr = n0 + w * 16 + g;

    const __nv_bfloat16* Kh = d_k_h + (size_t)b * Mm * Ci;
    const __nv_bfloat16* Kl = d_k_l + (size_t)b * Mm * Ci;
    const __nv_bfloat16* Vh = d_v_h + (size_t)b * Mm * Ci;
    const __nv_bfloat16* Vl = d_v_l + (size_t)b * Mm * Ci;

    load_tile_async(sKh, Kh); load_tile_async(sKl, Kl); CPC();
    load_tile_async(sVh, Vh); load_tile_async(sVl, Vl); CPC();

    uint32_t qh[32], ql[32];
    {
        const __nv_bfloat16* q0 = d_th_h + ((size_t)b * Nn + qr) * Ci;
        const __nv_bfloat16* q1 = q0 + 8 * Ci;
        const __nv_bfloat16* p0 = d_th_l + ((size_t)b * Nn + qr) * Ci;
        const __nv_bfloat16* p1 = p0 + 8 * Ci;
#pragma unroll
        for (int kc = 0; kc < 8; kc++) {
            int c0 = kc * 16 + tig2;
            qh[kc * 4 + 0] = *(const uint32_t*)(q0 + c0);
            qh[kc * 4 + 1] = *(const uint32_t*)(q1 + c0);
            qh[kc * 4 + 2] = *(const uint32_t*)(q0 + c0 + 8);
            qh[kc * 4 + 3] = *(const uint32_t*)(q1 + c0 + 8);
            ql[kc * 4 + 0] = *(const uint32_t*)(p0 + c0);
            ql[kc * 4 + 1] = *(const uint32_t*)(p1 + c0);
            ql[kc * 4 + 2] = *(const uint32_t*)(p0 + c0 + 8);
            ql[kc * 4 + 3] = *(const uint32_t*)(p1 + c0 + 8);
        }
    }

    const uint32_t lmoff  = (uint32_t)(((l & 7) | ((l >> 4) << 3)) * TPAD + ((l >> 3) & 1) * 16);
    const uint32_t lmoffV = (uint32_t)(((l & 7) | (((l >> 3) & 1) << 3)) * TPAD + (l >> 4) * 16);

    uint32_t P[64];
    float O[64];
#pragma unroll
    for (int i = 0; i < 64; i++) O[i] = 0.f;
    float l_lo = 0.f, l_hi = 0.f;

    for (int it = 0; it < 8; it++) {
        CPW1();
        __syncthreads();

        // ---- fused S = Q K^T + softmax numerator, per key-chunk np ----
#pragma unroll
        for (int np = 0; np < 8; np++) {
            float Sv[8];
#pragma unroll
            for (int i = 0; i < 8; i++) Sv[i] = 0.f;
            uint32_t kb  = sKh + np * 16 * TPAD + lmoff;
            uint32_t kb2 = sKl + np * 16 * TPAD + lmoff;
#pragma unroll
            for (int kc = 0; kc < 8; kc++) {
                uint32_t h0, h1, h2, h3, e0, e1, e2, e3;
                LDSM4(h0, h1, h2, h3, kb + kc * 32);
                LDSM4(e0, e1, e2, e3, kb2 + kc * 32);
                MMA16816(Sv,     qh + kc * 4, h0, h1);
                MMA16816(Sv,     ql + kc * 4, h0, h1);
                MMA16816(Sv,     qh + kc * 4, e0, e1);
                MMA16816(Sv + 4, qh + kc * 4, h2, h3);
                MMA16816(Sv + 4, ql + kc * 4, h2, h3);
                MMA16816(Sv + 4, qh + kc * 4, e2, e3);
            }
            float p[8];
#pragma unroll
            for (int i = 0; i < 8; i++) p[i] = __expf(Sv[i] - EXP_SHIFT);
            l_lo += (p[0] + p[1]) + (p[4] + p[5]);
            l_hi += (p[2] + p[3]) + (p[6] + p[7]);
            float hf[8], lf[8];
#pragma unroll
            for (int i = 0; i < 8; i++) {
                __nv_bfloat16 h = __float2bfloat16(p[i]);
                hf[i] = __bfloat162float(h);
                lf[i] = p[i] - hf[i];
            }
            P[np * 8 + 0] = pack_bf16x2(hf[0], hf[1]);
            P[np * 8 + 1] = pack_bf16x2(hf[2], hf[3]);
            P[np * 8 + 2] = pack_bf16x2(hf[4], hf[5]);
            P[np * 8 + 3] = pack_bf16x2(hf[6], hf[7]);
            P[np * 8 + 4] = pack_bf16x2(lf[0], lf[1]);
            P[np * 8 + 5] = pack_bf16x2(lf[2], lf[3]);
            P[np * 8 + 6] = pack_bf16x2(lf[4], lf[5]);
            P[np * 8 + 7] = pack_bf16x2(lf[6], lf[7]);
        }
        __syncthreads();

        CPW0();
        __syncthreads();

        if (it < 7) {
            load_tile_async(sKh, Kh + (size_t)(it + 1) * 128 * Ci);
            load_tile_async(sKl, Kl + (size_t)(it + 1) * 128 * Ci);
            CPC();
        }

#pragma unroll
        for (int np = 0; np < 8; np++) {
#pragma unroll
            for (int kc = 0; kc < 8; kc++) {
                uint32_t vb  = sVh + kc * 16 * TPAD + np * 32 + lmoffV;
                uint32_t vb2 = sVl + kc * 16 * TPAD + np * 32 + lmoffV;
                uint32_t h0, h1, h2, h3, e0, e1, e2, e3;
                LDSM4T(h0, h1, h2, h3, vb);
                LDSM4T(e0, e1, e2, e3, vb2);
                MMA16816(O + np * 8,     P + kc * 8,     h0, h1);
                MMA16816(O + np * 8,     P + kc * 8 + 4, h0, h1);
                MMA16816(O + np * 8,     P + kc * 8,     e0, e1);
                MMA16816(O + np * 8 + 4, P + kc * 8,     h2, h3);
                MMA16816(O + np * 8 + 4, P + kc * 8 + 4, h2, h3);
                MMA16816(O + np * 8 + 4, P + kc * 8,     e2, e3);
            }
        }
        __syncthreads();

        if (it < 7) {
            load_tile_async(sVh, Vh + (size_t)(it + 1) * 128 * Ci);
            load_tile_async(sVl, Vl + (size_t)(it + 1) * 128 * Ci);
            CPC();
        }
    }

    l_lo += __shfl_xor_sync(0xffffffffu, l_lo, 1);
    l_lo += __shfl_xor_sync(0xffffffffu, l_lo, 2);
    l_hi += __shfl_xor_sync(0xffffffffu, l_hi, 1);
    l_hi += __shfl_xor_sync(0xffffffffu, l_hi, 2);
    float i0 = 1.0f / l_lo, i1 = 1.0f / l_hi;

    size_t base0 = ((size_t)b * Nn + qr) * Ci;
    size_t base1 = base0 + 8 * Ci;
#pragma unroll
    for (int nb = 0; nb < 16; nb++) {
        float v0 = O[nb * 4 + 0] * i0, v1 = O[nb * 4 + 1] * i0;
        float v2 = O[nb * 4 + 2] * i1, v3 = O[nb * 4 + 3] * i1;
        __nv_bfloat16 h0, l0, h1, l1;
        split_bf16(v0, h0, l0); split_bf16(v1, h1, l1);
        *(uint32_t*)&d_o_h[base0 + nb * 8 + tig2] =
            (uint32_t)__bfloat16_as_ushort(h0) | ((uint32_t)__bfloat16_as_ushort(h1) << 16);
        *(uint32_t*)&d_o_l[base0 + nb * 8 + tig2] =
            (uint32_t)__bfloat16_as_ushort(l0) | ((uint32_t)__bfloat16_as_ushort(l1) << 16);
        split_bf16(v2, h0, l0); split_bf16(v3, h1, l1);
        *(uint32_t*)&d_o_h[base1 + nb * 8 + tig2] =
            (uint32_t)__bfloat16_as_ushort(h0) | ((uint32_t)__bfloat16_as_ushort(h1) << 16);
        *(uint32_t*)&d_o_l[base1 + nb * 8 + tig2] =
            (uint32_t)__bfloat16_as_ushort(l0) | ((uint32_t)__bfloat16_as_ushort(l1) << 16);
    }
}

// ---------------------------------------------------------------------------
// tensor-core W projection + fused BN stats, 2-stage cp.async pipelined.
// ---------------------------------------------------------------------------
#define WSTG 40960
#define WPROJ_SMEM 81920

__global__ __launch_bounds__(256, 2)
void wproj_mma_kernel(const __nv_bfloat16* __restrict__ w_h, const __nv_bfloat16* __restrict__ w_l,
                      const float* __restrict__ bias)
{
    extern __shared__ char dsm[];
    const uint32_t sb = smem_u32(dsm);

    const int b = blockIdx.z, cb0 = blockIdx.y << 7, n0 = blockIdx.x << 7;
    const int tid = threadIdx.x, w = tid >> 5, l = tid & 31;
    const int g = l >> 2, tig2 = (l & 3) * 2;

    const __nv_bfloat16* Bin_h = d_o_h + ((size_t)b * Nn + n0) * Ci;
    const __nv_bfloat16* Bin_l = d_o_l + ((size_t)b * Nn + n0) * Ci;

    const uint32_t lmoff = (uint32_t)((((l & 7) | ((l >> 4) << 3)) * 80) + ((l >> 3) & 1) * 16);

    {
        const int k0 = 0;
        uint32_t st = sb;
#pragma unroll
        for (int p = 0; p < 8; p++) {
            int f = tid + (p << 8);
            int buf = f >> 9, idx = f & 511;
            int row = idx >> 2, seg = idx & 3;
            const __nv_bfloat16* src =
                (buf == 0) ? w_h   + (size_t)(cb0 + row) * Ci + k0 + seg * 8 :
                (buf == 1) ? w_l   + (size_t)(cb0 + row) * Ci + k0 + seg * 8 :
                (buf == 2) ? Bin_h + (size_t)row * Ci + k0 + seg * 8 :
                             Bin_l + (size_t)row * Ci + k0 + seg * 8;
            CPA16(st + (uint32_t)(buf * 10240 + row * 80 + seg * 16), src);
        }
        CPC();
    }

    float acc[64];
#pragma unroll
    for (int i = 0; i < 64; i++) acc[i] = 0.f;

    for (int c = 0; c < 4; c++) {
        if (c < 3) {
            const int k0 = (c + 1) * 32;
            uint32_t st = sb + ((c + 1) & 1) * WSTG;
#pragma unroll
            for (int p = 0; p < 8; p++) {
                int f = tid + (p << 8);
                int buf = f >> 9, idx = f & 511;
                int row = idx >> 2, seg = idx & 3;
                const __nv_bfloat16* src =
                    (buf == 0) ? w_h   + (size_t)(cb0 + row) * Ci + k0 + seg * 8 :
                    (buf == 1) ? w_l   + (size_t)(cb0 + row) * Ci + k0 + seg * 8 :
                    (buf == 2) ? Bin_h + (size_t)row * Ci + k0 + seg * 8 :
                                 Bin_l + (size_t)row * Ci + k0 + seg * 8;
                CPA16(st + (uint32_t)(buf * 10240 + row * 80 + seg * 16), src);
            }
            CPC();
            CPW1();
        } else {
            CPW0();
        }
        __syncthreads();

        const uint32_t st = sb + (c & 1) * WSTG;
        const uint32_t sAh = st, sAl = st + 10240, sBh = st + 20480, sBl = st + 30720;

#pragma unroll
        for (int kc = 0; kc < 2; kc++) {
            uint32_t aH[4], aL[4];
            uint32_t abase = w * 16 * 80 + lmoff + kc * 32;
            LDSM4(aH[0], aH[2], aH[1], aH[3], sAh + abase);
            LDSM4(aL[0], aL[2], aL[1], aL[3], sAl + abase);
#pragma unroll
            for (int np = 0; np < 8; np++) {
                uint32_t bbase = np * 16 * 80 + lmoff + kc * 32;
                uint32_t h0, h1, h2, h3, e0, e1, e2, e3;
                LDSM4(h0, h1, h2, h3, sBh + bbase);
                LDSM4(e0, e1, e2, e3, sBl + bbase);
                MMA16816(acc + (np * 2 + 0) * 4, aH, h0, h1);
                MMA16816(acc + (np * 2 + 0) * 4, aL, h0, h1);
                MMA16816(acc + (np * 2 + 0) * 4, aH, e0, e1);
                MMA16816(acc + (np * 2 + 1) * 4, aH, h2, h3);
                MMA16816(acc + (np * 2 + 1) * 4, aL, h2, h3);
                MMA16816(acc + (np * 2 + 1) * 4, aH, e2, e3);
            }
        }
        __syncthreads();
    }

    const int c0 = cb0 + w * 16 + g;
    float bv0 = __ldg(&bias[c0]), bv1 = __ldg(&bias[c0 + 8]);
    float s0 = 0.f, q0 = 0.f, s1 = 0.f, q1 = 0.f;
#pragma unroll
    for (int j = 0; j < 16; j++) {
        int ncol = n0 + (j >> 1) * 16 + (j & 1) * 8 + tig2;
        float v0 = acc[j * 4 + 0] + bv0, v1 = acc[j * 4 + 1] + bv0;
        float v2 = acc[j * 4 + 2] + bv1, v3 = acc[j * 4 + 3] + bv1;
        s0 += v0 + v1; q0 += v0 * v0 + v1 * v1;
        s1 += v2 + v3; q1 += v2 * v2 + v3 * v3;
        *(float2*)&d_wy[((size_t)b * Cc + c0) * Nn + ncol]     = make_float2(v0, v1);
        *(float2*)&d_wy[((size_t)b * Cc + c0 + 8) * Nn + ncol] = make_float2(v2, v3);
    }
    s0 += __shfl_xor_sync(0xffffffffu, s0, 1); s0 += __shfl_xor_sync(0xffffffffu, s0, 2);
    q0 += __shfl_xor_sync(0xffffffffu, q0, 1); q0 += __shfl_xor_sync(0xffffffffu, q0, 2);
    s1 += __shfl_xor_sync(0xffffffffu, s1, 1); s1 += __shfl_xor_sync(0xffffffffu, s1, 2);
    q1 += __shfl_xor_sync(0xffffffffu, q1, 1); q1 += __shfl_xor_sync(0xffffffffu, q1, 2);
    if ((l & 3) == 0) {
        atomicAdd(&d_bnacc[c0], s0);          atomicAdd(&d_bnacc[Cc + c0], q0);
        atomicAdd(&d_bnacc[c0 + 8], s1);      atomicAdd(&d_bnacc[Cc + c0 + 8], q1);
    }
}

// ------- finalize: BN stats inline + affine + residual (no stats kernel) ----
__global__ void finalize_kernel(const float* __restrict__ x,
                                const float* __restrict__ gamma,
                                const float* __restrict__ beta,
                                float* __restrict__ out)
{
    size_t i4 = (size_t)blockIdx.x * blockDim.x + threadIdx.x;
    size_t total4 = (size_t)Bn * Cc * Nn / 4;
    if (i4 >= total4) return;
    size_t i = i4 * 4;
    int c = (int)((i >> 12) & (Cc - 1));
    const float inv = 1.0f / (float)(Bn * Nn);
    float mean = __ldg(&d_bnacc[c]) * inv;
    float var = fmaxf(__ldg(&d_bnacc[Cc + c]) * inv - mean * mean, 0.f);
    float rstd = rsqrtf(var + 1e-5f);
    float ga = __ldg(&gamma[c]) * rstd;
    float be = __ldg(&beta[c]);
    float4 w  = *(const float4*)&d_wy[i];
    float4 xv = *(const float4*)&x[i];
    float4 o;
    o.x = (w.x - mean) * ga + be + xv.x;
    o.y = (w.y - mean) * ga + be + xv.y;
    o.z = (w.z - mean) * ga + be + xv.z;
    o.w = (w.w - mean) * ga + be + xv.w;
    *(float4*)&out[i] = o;
}

// ---------------------------------------------------------------------------
extern "C" void kernel_launch(void* const* d_in, const int* in_sizes, int n_in,
                              void* d_out, int out_size)
{
    const float* x       = (const float*)d_in[0];
    const float* y       = (const float*)d_in[1];
    const float* theta_w = (const float*)d_in[2];
    const float* theta_b = (const float*)d_in[3];
    const float* phi_w   = (const float*)d_in[4];
    const float* phi_b   = (const float*)d_in[5];
    const float* g_w     = (const float*)d_in[6];
    const float* g_b     = (const float*)d_in[7];
    const float* w_w     = (const float*)d_in[8];
    const float* w_b     = (const float*)d_in[9];
    const float* gamma   = (const float*)d_in[10];
    const float* beta    = (const float*)d_in[11];
    float* out = (float*)d_out;

    cudaFuncSetAttribute(attn_mma_kernel, cudaFuncAttributeMaxDynamicSharedMemorySize, ATT_SMEM);
    cudaFuncSetAttribute(conv_mma_kernel, cudaFuncAttributeMaxDynamicSharedMemorySize, CONV_SMEM);
    cudaFuncSetAttribute(wproj_mma_kernel, cudaFuncAttributeMaxDynamicSharedMemorySize, WPROJ_SMEM);

    __nv_bfloat16 *wh_p, *wl_p, *thh, *thl, *kh, *kl, *vh, *vl;
    float *bnacc_p;
    cudaGetSymbolAddress((void**)&wh_p, d_wh);
    cudaGetSymbolAddress((void**)&wl_p, d_wl);
    cudaGetSymbolAddress((void**)&thh, d_th_h);
    cudaGetSymbolAddress((void**)&thl, d_th_l);
    cudaGetSymbolAddress((void**)&kh,  d_k_h);
    cudaGetSymbolAddress((void**)&kl,  d_k_l);
    cudaGetSymbolAddress((void**)&vh,  d_v_h);
    cudaGetSymbolAddress((void**)&vl,  d_v_l);
    cudaGetSymbolAddress((void**)&bnacc_p, d_bnacc);

    cudaMemsetAsync(bnacc_p, 0, 2 * Cc * sizeof(float));

    split_w_kernel<<<512, 256>>>(theta_w, phi_w, g_w, w_w);

    dim3 gConv(Nn / 128, Bn);
    conv_mma_kernel<<<gConv, 256, CONV_SMEM>>>(x, wh_p, wl_p, theta_b, thh, thl, 0);
    conv_mma_kernel<<<gConv, 256, CONV_SMEM>>>(y, wh_p + 32768, wl_p + 32768, phi_b, kh, kl, 1);
    conv_mma_kernel<<<gConv, 256, CONV_SMEM>>>(y, wh_p + 2 * 32768, wl_p + 2 * 32768, g_b, vh, vl, 1);

    attn_mma_kernel<<<dim3(Nn / 128, Bn), 256, ATT_SMEM>>>();

    wproj_mma_kernel<<<dim3(Nn / 128, Cc / 128, Bn), 256, WPROJ_SMEM>>>(wh_p + 3 * 32768, wl_p + 3 * 32768, w_b);
    finalize_kernel<<<(Bn * Cc * Nn / 4 + 255) / 256, 256>>>(x, gamma, beta, out);
}

// round 16
// speedup vs baseline: 1.0447x; 1.0076x over previous
#include <cuda_runtime.h>
#include <cuda_bf16.h>
#include <cstdint>

#define Bn 8
#define Cc 256
#define Ci 128
#define Nn 4096   // 64*64
#define Mm 1024   // 32*32

// ---------------- scratch (static device allocations; no cudaMalloc) ------
__device__ __nv_bfloat16 d_wh  [4 * 32768];             // weight splits (theta,phi,g,w)
__device__ __nv_bfloat16 d_wl  [4 * 32768];
__device__ __nv_bfloat16 d_th_h[(size_t)Bn * Nn * Ci];  // theta hi [b][n][ci]
__device__ __nv_bfloat16 d_th_l[(size_t)Bn * Nn * Ci];
__device__ __nv_bfloat16 d_k_h [(size_t)Bn * Mm * Ci];  // K hi [b][m][ci]
__device__ __nv_bfloat16 d_k_l [(size_t)Bn * Mm * Ci];
__device__ __nv_bfloat16 d_v_h [(size_t)Bn * Mm * Ci];  // V hi [b][m][ci]
__device__ __nv_bfloat16 d_v_l [(size_t)Bn * Mm * Ci];
__device__ __nv_bfloat16 d_o_h [(size_t)Bn * Nn * Ci];  // attn out hi [b][n][ci]
__device__ __nv_bfloat16 d_o_l [(size_t)Bn * Nn * Ci];
__device__ float d_wy   [(size_t)Bn * Cc * Nn];         // [b][c][n]
__device__ float d_bnacc[2 * Cc];                       // BN partial sums (sum | sumsq)

__device__ __forceinline__ uint32_t smem_u32(const void* p) {
    uint32_t a;
    asm("{ .reg .u64 t; cvta.to.shared.u64 t, %1; cvt.u32.u64 %0, t; }" : "=r"(a) : "l"(p));
    return a;
}
__device__ __forceinline__ uint32_t pack_bf16x2(float lo, float hi) {
    __nv_bfloat16 a = __float2bfloat16(lo), b = __float2bfloat16(hi);
    return (uint32_t)__bfloat16_as_ushort(a) | ((uint32_t)__bfloat16_as_ushort(b) << 16);
}
__device__ __forceinline__ void split_bf16(float v, __nv_bfloat16& h, __nv_bfloat16& l) {
    h = __float2bfloat16(v);
    l = __float2bfloat16(v - __bfloat162float(h));
}

#define LDSM4(r0, r1, r2, r3, addr) \
    asm volatile("ldmatrix.sync.aligned.m8n8.x4.shared.b16 {%0,%1,%2,%3}, [%4];" \
        : "=r"(r0), "=r"(r1), "=r"(r2), "=r"(r3) : "r"(addr))
#define LDSM4T(r0, r1, r2, r3, addr) \
    asm volatile("ldmatrix.sync.aligned.m8n8.x4.trans.shared.b16 {%0,%1,%2,%3}, [%4];" \
        : "=r"(r0), "=r"(r1), "=r"(r2), "=r"(r3) : "r"(addr))

#define MMA16816(C, A, b0, b1) \
    asm volatile("mma.sync.aligned.m16n8k16.row.col.f32.bf16.bf16.f32 " \
        "{%0,%1,%2,%3}, {%4,%5,%6,%7}, {%8,%9}, {%0,%1,%2,%3};" \
        : "+f"((C)[0]), "+f"((C)[1]), "+f"((C)[2]), "+f"((C)[3]) \
        : "r"((A)[0]), "r"((A)[1]), "r"((A)[2]), "r"((A)[3]), "r"(b0), "r"(b1))

#define CPA16(dst, src) \
    asm volatile("cp.async.cg.shared.global [%0], [%1], 16;" :: "r"(dst), "l"(src))
#define CPC() asm volatile("cp.async.commit_group;" ::: "memory")
#define CPW0() asm volatile("cp.async.wait_group 0;" ::: "memory")
#define CPW1() asm volatile("cp.async.wait_group 1;" ::: "memory")

// ---------------------------------------------------------------------------
// split all 4 weight matrices into bf16 hi/lo (elementwise)
// ---------------------------------------------------------------------------
__global__ void split_w_kernel(const float* __restrict__ tw, const float* __restrict__ pw,
                               const float* __restrict__ gw, const float* __restrict__ ww)
{
    int idx = blockIdx.x * blockDim.x + threadIdx.x;
    int seg = idx >> 15, off = idx & 32767;
    const float* src = (seg == 0) ? tw : (seg == 1) ? pw : (seg == 2) ? gw : ww;
    float v = src[off];
    __nv_bfloat16 h, l;
    split_bf16(v, h, l);
    d_wh[idx] = h; d_wl[idx] = l;
}

// ---------------------------------------------------------------------------
// tensor-core conv1x1 (theta path), reads fp32 X [b][c][n] directly.
// bf16 hi/lo epilogue -> out_h/out_l [b][n][ci]
// ---------------------------------------------------------------------------
#define APITCH 132
#define CSTG 37376
#define CONV_SMEM 74752

__global__ __launch_bounds__(256, 2)
void conv_mma_kernel(const float* __restrict__ X,
                     const __nv_bfloat16* __restrict__ w_h, const __nv_bfloat16* __restrict__ w_l,
                     const float* __restrict__ bias,
                     __nv_bfloat16* __restrict__ out_h, __nv_bfloat16* __restrict__ out_l)
{
    extern __shared__ char dsm[];
    const uint32_t sb = smem_u32(dsm);

    const int b = blockIdx.y, n0 = blockIdx.x << 7;
    const int tid = threadIdx.x, w = tid >> 5, l = tid & 31;
    const int g = l >> 2, tig2 = (l & 3) * 2;

    const float* Ain = X + (size_t)b * Cc * Nn + n0;

    const uint32_t lmoff = (uint32_t)((((l & 7) | ((l >> 4) << 3)) * 80) + ((l >> 3) & 1) * 16);

    {
        uint32_t st = sb;
#pragma unroll
        for (int p = 0; p < 4; p++) {
            int f = tid + (p << 8);
            int row = f >> 5, seg = f & 31;
            CPA16(st + (uint32_t)(row * 528 + seg * 16), Ain + (size_t)row * Nn + seg * 4);
        }
#pragma unroll
        for (int p = 0; p < 4; p++) {
            int f = tid + (p << 8);
            int buf = f >> 9, idx = f & 511;
            int row = idx >> 2, seg = idx & 3;
            const __nv_bfloat16* src = (buf ? w_l : w_h) + (size_t)row * Cc + seg * 8;
            CPA16(st + (uint32_t)(16896 + buf * 10240 + row * 80 + seg * 16), src);
        }
        CPC();
    }

    float acc[64];
#pragma unroll
    for (int i = 0; i < 64; i++) acc[i] = 0.f;

    for (int c = 0; c < 8; c++) {
        if (c < 7) {
            const int k0 = (c + 1) * 32;
            uint32_t st = sb + ((c + 1) & 1) * CSTG;
#pragma unroll
            for (int p = 0; p < 4; p++) {
                int f = tid + (p << 8);
                int row = f >> 5, seg = f & 31;
                CPA16(st + (uint32_t)(row * 528 + seg * 16), Ain + (size_t)(k0 + row) * Nn + seg * 4);
            }
#pragma unroll
            for (int p = 0; p < 4; p++) {
                int f = tid + (p << 8);
                int buf = f >> 9, idx = f & 511;
                int row = idx >> 2, seg = idx & 3;
                const __nv_bfloat16* src = (buf ? w_l : w_h) + (size_t)row * Cc + k0 + seg * 8;
                CPA16(st + (uint32_t)(16896 + buf * 10240 + row * 80 + seg * 16), src);
            }
            CPC();
            CPW1();
        } else {
            CPW0();
        }
        __syncthreads();

        const float* As = (const float*)(dsm + (c & 1) * CSTG);
        const uint32_t st = sb + (c & 1) * CSTG;
        const uint32_t sBh = st + 16896, sBl = st + 27136;

#pragma unroll
        for (int kc = 0; kc < 2; kc++) {
            uint32_t aH[4], aL[4];
            const int kb = kc * 16 + tig2;
#pragma unroll
            for (int p = 0; p < 4; p++) {
                int k = kb + (p >> 1) * 8;
                int n = w * 16 + g + (p & 1) * 8;
                float v0 = As[k * APITCH + n];
                float v1 = As[(k + 1) * APITCH + n];
                __nv_bfloat16 h0, l0, h1, l1;
                split_bf16(v0, h0, l0); split_bf16(v1, h1, l1);
                aH[p] = (uint32_t)__bfloat16_as_ushort(h0) | ((uint32_t)__bfloat16_as_ushort(h1) << 16);
                aL[p] = (uint32_t)__bfloat16_as_ushort(l0) | ((uint32_t)__bfloat16_as_ushort(l1) << 16);
            }
#pragma unroll
            for (int np = 0; np < 8; np++) {
                uint32_t bbase = np * 16 * 80 + lmoff + kc * 32;
                uint32_t h0, h1, h2, h3, e0, e1, e2, e3;
                LDSM4(h0, h1, h2, h3, sBh + bbase);
                LDSM4(e0, e1, e2, e3, sBl + bbase);
                MMA16816(acc + (np * 2 + 0) * 4, aH, h0, h1);
                MMA16816(acc + (np * 2 + 0) * 4, aL, h0, h1);
                MMA16816(acc + (np * 2 + 0) * 4, aH, e0, e1);
                MMA16816(acc + (np * 2 + 1) * 4, aH, h2, h3);
                MMA16816(acc + (np * 2 + 1) * 4, aL, h2, h3);
                MMA16816(acc + (np * 2 + 1) * 4, aH, e2, e3);
            }
        }
        __syncthreads();
    }

    const int r0 = n0 + w * 16 + g;
#pragma unroll
    for (int j = 0; j < 16; j++) {
        int cb = (j >> 1) * 16 + (j & 1) * 8 + tig2;
        float b0 = __ldg(&bias[cb]), b1 = __ldg(&bias[cb + 1]);
        float v0 = acc[j * 4 + 0] + b0, v1 = acc[j * 4 + 1] + b1;
        float v2 = acc[j * 4 + 2] + b0, v3 = acc[j * 4 + 3] + b1;
        size_t p0 = ((size_t)b * Nn + r0) * Ci + cb;
        size_t p1 = p0 + 8 * Ci;
        __nv_bfloat16 h0, l0, h1, l1;
        split_bf16(v0, h0, l0); split_bf16(v1, h1, l1);
        *(uint32_t*)&out_h[p0] = (uint32_t)__bfloat16_as_ushort(h0) | ((uint32_t)__bfloat16_as_ushort(h1) << 16);
        *(uint32_t*)&out_l[p0] = (uint32_t)__bfloat16_as_ushort(l0) | ((uint32_t)__bfloat16_as_ushort(l1) << 16);
        split_bf16(v2, h0, l0); split_bf16(v3, h1, l1);
        *(uint32_t*)&out_h[p1] = (uint32_t)__bfloat16_as_ushort(h0) | ((uint32_t)__bfloat16_as_ushort(h1) << 16);
        *(uint32_t*)&out_l[p1] = (uint32_t)__bfloat16_as_ushort(l0) | ((uint32_t)__bfloat16_as_ushort(l1) << 16);
    }
}

// ---------------------------------------------------------------------------
// merged phi+g conv: reads y tile ONCE, runs both weight sets' MMAs.
// 2-stage: A fp32 16896 + 4 weight bufs (Ph,Pl,Gh,Gl) 10240 each = 57856/stage.
// Epilogue pools both (2x2 max) -> K [b][m][ci] and V [b][m][ci] bf16 hi/lo.
// ---------------------------------------------------------------------------
#define C2STG 57856
#define CONV2_SMEM 115712

__global__ __launch_bounds__(256, 1)
void conv2_mma_kernel(const float* __restrict__ Y,
                      const __nv_bfloat16* __restrict__ pw_h, const __nv_bfloat16* __restrict__ pw_l,
                      const __nv_bfloat16* __restrict__ gw_h, const __nv_bfloat16* __restrict__ gw_l,
                      const float* __restrict__ pbias, const float* __restrict__ gbias)
{
    extern __shared__ char dsm[];
    const uint32_t sb = smem_u32(dsm);

    const int b = blockIdx.y, n0 = blockIdx.x << 7;
    const int tid = threadIdx.x, w = tid >> 5, l = tid & 31;
    const int g = l >> 2, tig2 = (l & 3) * 2;

    const float* Ain = Y + (size_t)b * Cc * Nn + n0;

    const uint32_t lmoff = (uint32_t)((((l & 7) | ((l >> 4) << 3)) * 80) + ((l >> 3) & 1) * 16);

    // issue chunk 0
    {
        uint32_t st = sb;
#pragma unroll
        for (int p = 0; p < 4; p++) {
            int f = tid + (p << 8);
            int row = f >> 5, seg = f & 31;
            CPA16(st + (uint32_t)(row * 528 + seg * 16), Ain + (size_t)row * Nn + seg * 4);
        }
#pragma unroll
        for (int p = 0; p < 8; p++) {
            int f = tid + (p << 8);
            int buf = f >> 9, idx = f & 511;
            int row = idx >> 2, seg = idx & 3;
            const __nv_bfloat16* src =
                (buf == 0) ? pw_h + (size_t)row * Cc + seg * 8 :
                (buf == 1) ? pw_l + (size_t)row * Cc + seg * 8 :
                (buf == 2) ? gw_h + (size_t)row * Cc + seg * 8 :
                             gw_l + (size_t)row * Cc + seg * 8;
            CPA16(st + (uint32_t)(16896 + buf * 10240 + row * 80 + seg * 16), src);
        }
        CPC();
    }

    float accP[64], accG[64];
#pragma unroll
    for (int i = 0; i < 64; i++) { accP[i] = 0.f; accG[i] = 0.f; }

    for (int c = 0; c < 8; c++) {
        if (c < 7) {
            const int k0 = (c + 1) * 32;
            uint32_t st = sb + ((c + 1) & 1) * C2STG;
#pragma unroll
            for (int p = 0; p < 4; p++) {
                int f = tid + (p << 8);
                int row = f >> 5, seg = f & 31;
                CPA16(st + (uint32_t)(row * 528 + seg * 16), Ain + (size_t)(k0 + row) * Nn + seg * 4);
            }
#pragma unroll
            for (int p = 0; p < 8; p++) {
                int f = tid + (p << 8);
                int buf = f >> 9, idx = f & 511;
                int row = idx >> 2, seg = idx & 3;
                const __nv_bfloat16* src =
                    (buf == 0) ? pw_h + (size_t)row * Cc + k0 + seg * 8 :
                    (buf == 1) ? pw_l + (size_t)row * Cc + k0 + seg * 8 :
                    (buf == 2) ? gw_h + (size_t)row * Cc + k0 + seg * 8 :
                                 gw_l + (size_t)row * Cc + k0 + seg * 8;
                CPA16(st + (uint32_t)(16896 + buf * 10240 + row * 80 + seg * 16), src);
            }
            CPC();
            CPW1();
        } else {
            CPW0();
        }
        __syncthreads();

        const float* As = (const float*)(dsm + (c & 1) * C2STG);
        const uint32_t st = sb + (c & 1) * C2STG;
        const uint32_t sPh = st + 16896, sPl = st + 27136;
        const uint32_t sGh = st + 37376, sGl = st + 47616;

#pragma unroll
        for (int kc = 0; kc < 2; kc++) {
            uint32_t aH[4], aL[4];
            const int kb = kc * 16 + tig2;
#pragma unroll
            for (int p = 0; p < 4; p++) {
                int k = kb + (p >> 1) * 8;
                int n = w * 16 + g + (p & 1) * 8;
                float v0 = As[k * APITCH + n];
                float v1 = As[(k + 1) * APITCH + n];
                __nv_bfloat16 h0, l0, h1, l1;
                split_bf16(v0, h0, l0); split_bf16(v1, h1, l1);
                aH[p] = (uint32_t)__bfloat16_as_ushort(h0) | ((uint32_t)__bfloat16_as_ushort(h1) << 16);
                aL[p] = (uint32_t)__bfloat16_as_ushort(l0) | ((uint32_t)__bfloat16_as_ushort(l1) << 16);
            }
#pragma unroll
            for (int np = 0; np < 8; np++) {
                uint32_t bbase = np * 16 * 80 + lmoff + kc * 32;
                uint32_t h0, h1, h2, h3, e0, e1, e2, e3;
                LDSM4(h0, h1, h2, h3, sPh + bbase);
                LDSM4(e0, e1, e2, e3, sPl + bbase);
                MMA16816(accP + (np * 2 + 0) * 4, aH, h0, h1);
                MMA16816(accP + (np * 2 + 0) * 4, aL, h0, h1);
                MMA16816(accP + (np * 2 + 0) * 4, aH, e0, e1);
                MMA16816(accP + (np * 2 + 1) * 4, aH, h2, h3);
                MMA16816(accP + (np * 2 + 1) * 4, aL, h2, h3);
                MMA16816(accP + (np * 2 + 1) * 4, aH, e2, e3);
                LDSM4(h0, h1, h2, h3, sGh + bbase);
                LDSM4(e0, e1, e2, e3, sGl + bbase);
                MMA16816(accG + (np * 2 + 0) * 4, aH, h0, h1);
                MMA16816(accG + (np * 2 + 0) * 4, aL, h0, h1);
                MMA16816(accG + (np * 2 + 0) * 4, aH, e0, e1);
                MMA16816(accG + (np * 2 + 1) * 4, aH, h2, h3);
                MMA16816(accG + (np * 2 + 1) * 4, aL, h2, h3);
                MMA16816(accG + (np * 2 + 1) * 4, aH, e2, e3);
            }
        }
        __syncthreads();
    }

    // ---- epilogue: pool accP -> K, then accG -> V ----
    float* pb = (float*)dsm;   // [128][132]
    const int r0 = w * 16 + g;
    const int m0 = blockIdx.x << 5;

#pragma unroll
    for (int pass = 0; pass < 2; pass++) {
        const float* acc = pass ? accG : accP;
        const float* bias = pass ? gbias : pbias;
        __nv_bfloat16* oh = pass ? d_v_h : d_k_h;
        __nv_bfloat16* ol = pass ? d_v_l : d_k_l;
#pragma unroll
        for (int j = 0; j < 16; j++) {
            int cb = (j >> 1) * 16 + (j & 1) * 8 + tig2;
            float b0 = __ldg(&bias[cb]), b1 = __ldg(&bias[cb + 1]);
            pb[r0 * 132 + cb]           = acc[j * 4 + 0] + b0;
            pb[r0 * 132 + cb + 1]       = acc[j * 4 + 1] + b1;
            pb[(r0 + 8) * 132 + cb]     = acc[j * 4 + 2] + b0;
            pb[(r0 + 8) * 132 + cb + 1] = acc[j * 4 + 3] + b1;
        }
        __syncthreads();
#pragma unroll
        for (int rep = 0; rep < 16; rep++) {
            int idx = tid + rep * 256;
            int pj = idx >> 7, ci = idx & 127;
            int rA = pj * 2;
            float v = fmaxf(fmaxf(pb[rA * 132 + ci],        pb[(rA + 1) * 132 + ci]),
                            fmaxf(pb[(rA + 64) * 132 + ci], pb[(rA + 65) * 132 + ci]));
            __nv_bfloat16 h, lo;
            split_bf16(v, h, lo);
            size_t o = ((size_t)b * Mm + m0 + pj) * Ci + ci;
            oh[o] = h; ol[o] = lo;
        }
        __syncthreads();
    }
}

// ---------------------------------------------------------------------------
// mma.sync attention (R9 config): softmax fused per key chunk, Q in registers.
// CTA: 8 warps x 16 query rows; 8 key tiles of 128; 1 CTA/SM.
// ---------------------------------------------------------------------------
#define TPAD 272
#define TILE_BYTES (128 * TPAD)            // 34816
#define ATT_SMEM (4 * TILE_BYTES)          // 139264
#define EXP_SHIFT 40.0f

__device__ __forceinline__ void load_tile_async(uint32_t dst, const __nv_bfloat16* src)
{
    for (int f = threadIdx.x; f < 2048; f += 256) {
        int row = f >> 4, seg = f & 15;
        CPA16(dst + (uint32_t)(row * TPAD + seg * 16), src + (size_t)row * Ci + seg * 8);
    }
}

__global__ __launch_bounds__(256, 1) void attn_mma_kernel()
{
    extern __shared__ char smem[];
    const uint32_t sb = smem_u32(smem);
    const uint32_t sKh = sb, sKl = sb + TILE_BYTES;
    const uint32_t sVh = sb + 2 * TILE_BYTES, sVl = sb + 3 * TILE_BYTES;

    const int b = blockIdx.y, n0 = blockIdx.x << 7;
    const int tid = threadIdx.x, w = tid >> 5, l = tid & 31;
    const int g = l >> 2, tig2 = (l & 3) * 2;
    const int qr = n0 + w * 16 + g;

    const __nv_bfloat16* Kh = d_k_h + (size_t)b * Mm * Ci;
    const __nv_bfloat16* Kl = d_k_l + (size_t)b * Mm * Ci;
    const __nv_bfloat16* Vh = d_v_h + (size_t)b * Mm * Ci;
    const __nv_bfloat16* Vl = d_v_l + (size_t)b * Mm * Ci;

    load_tile_async(sKh, Kh); load_tile_async(sKl, Kl); CPC();
    load_tile_async(sVh, Vh); load_tile_async(sVl, Vl); CPC();

    uint32_t qh[32], ql[32];
    {
        const __nv_bfloat16* q0 = d_th_h + ((size_t)b * Nn + qr) * Ci;
        const __nv_bfloat16* q1 = q0 + 8 * Ci;
        const __nv_bfloat16* p0 = d_th_l + ((size_t)b * Nn + qr) * Ci;
        const __nv_bfloat16* p1 = p0 + 8 * Ci;
#pragma unroll
        for (int kc = 0; kc < 8; kc++) {
            int c0 = kc * 16 + tig2;
            qh[kc * 4 + 0] = *(const uint32_t*)(q0 + c0);
            qh[kc * 4 + 1] = *(const uint32_t*)(q1 + c0);
            qh[kc * 4 + 2] = *(const uint32_t*)(q0 + c0 + 8);
            qh[kc * 4 + 3] = *(const uint32_t*)(q1 + c0 + 8);
            ql[kc * 4 + 0] = *(const uint32_t*)(p0 + c0);
            ql[kc * 4 + 1] = *(const uint32_t*)(p1 + c0);
            ql[kc * 4 + 2] = *(const uint32_t*)(p0 + c0 + 8);
            ql[kc * 4 + 3] = *(const uint32_t*)(p1 + c0 + 8);
        }
    }

    const uint32_t lmoff  = (uint32_t)(((l & 7) | ((l >> 4) << 3)) * TPAD + ((l >> 3) & 1) * 16);
    const uint32_t lmoffV = (uint32_t)(((l & 7) | (((l >> 3) & 1) << 3)) * TPAD + (l >> 4) * 16);

    uint32_t P[64];
    float O[64];
#pragma unroll
    for (int i = 0; i < 64; i++) O[i] = 0.f;
    float l_lo = 0.f, l_hi = 0.f;

    for (int it = 0; it < 8; it++) {
        CPW1();
        __syncthreads();

        // ---- fused S = Q K^T + softmax numerator, per key-chunk np ----
#pragma unroll
        for (int np = 0; np < 8; np++) {
            float Sv[8];
#pragma unroll
            for (int i = 0; i < 8; i++) Sv[i] = 0.f;
            uint32_t kb  = sKh + np * 16 * TPAD + lmoff;
            uint32_t kb2 = sKl + np * 16 * TPAD + lmoff;
#pragma unroll
            for (int kc = 0; kc < 8; kc++) {
                uint32_t h0, h1, h2, h3, e0, e1, e2, e3;
                LDSM4(h0, h1, h2, h3, kb + kc * 32);
                LDSM4(e0, e1, e2, e3, kb2 + kc * 32);
                MMA16816(Sv,     qh + kc * 4, h0, h1);
                MMA16816(Sv,     ql + kc * 4, h0, h1);
                MMA16816(Sv,     qh + kc * 4, e0, e1);
                MMA16816(Sv + 4, qh + kc * 4, h2, h3);
                MMA16816(Sv + 4, ql + kc * 4, h2, h3);
                MMA16816(Sv + 4, qh + kc * 4, e2, e3);
            }
            float p[8];
#pragma unroll
            for (int i = 0; i < 8; i++) p[i] = __expf(Sv[i] - EXP_SHIFT);
            l_lo += (p[0] + p[1]) + (p[4] + p[5]);
            l_hi += (p[2] + p[3]) + (p[6] + p[7]);
            float hf[8], lf[8];
#pragma unroll
            for (int i = 0; i < 8; i++) {
                __nv_bfloat16 h = __float2bfloat16(p[i]);
                hf[i] = __bfloat162float(h);
                lf[i] = p[i] - hf[i];
            }
            P[np * 8 + 0] = pack_bf16x2(hf[0], hf[1]);
            P[np * 8 + 1] = pack_bf16x2(hf[2], hf[3]);
            P[np * 8 + 2] = pack_bf16x2(hf[4], hf[5]);
            P[np * 8 + 3] = pack_bf16x2(hf[6], hf[7]);
            P[np * 8 + 4] = pack_bf16x2(lf[0], lf[1]);
            P[np * 8 + 5] = pack_bf16x2(lf[2], lf[3]);
            P[np * 8 + 6] = pack_bf16x2(lf[4], lf[5]);
            P[np * 8 + 7] = pack_bf16x2(lf[6], lf[7]);
        }

        CPW0();            // V(it) arrived (own thread's groups)
        __syncthreads();   // publishes V across warps AND retires all S-phase K reads

        if (it < 7) {
            load_tile_async(sKh, Kh + (size_t)(it + 1) * 128 * Ci);
            load_tile_async(sKl, Kl + (size_t)(it + 1) * 128 * Ci);
            CPC();
        }

#pragma unroll
        for (int np = 0; np < 8; np++) {
#pragma unroll
            for (int kc = 0; kc < 8; kc++) {
                uint32_t vb  = sVh + kc * 16 * TPAD + np * 32 + lmoffV;
                uint32_t vb2 = sVl + kc * 16 * TPAD + np * 32 + lmoffV;
                uint32_t h0, h1, h2, h3, e0, e1, e2, e3;
                LDSM4T(h0, h1, h2, h3, vb);
                LDSM4T(e0, e1, e2, e3, vb2);
                MMA16816(O + np * 8,     P + kc * 8,     h0, h1);
                MMA16816(O + np * 8,     P + kc * 8 + 4, h0, h1);
                MMA16816(O + np * 8,     P + kc * 8,     e0, e1);
                MMA16816(O + np * 8 + 4, P + kc * 8,     h2, h3);
                MMA16816(O + np * 8 + 4, P + kc * 8 + 4, h2, h3);
                MMA16816(O + np * 8 + 4, P + kc * 8,     e2, e3);
            }
        }
        __syncthreads();

        if (it < 7) {
            load_tile_async(sVh, Vh + (size_t)(it + 1) * 128 * Ci);
            load_tile_async(sVl, Vl + (size_t)(it + 1) * 128 * Ci);
            CPC();
        }
    }

    l_lo += __shfl_xor_sync(0xffffffffu, l_lo, 1);
    l_lo += __shfl_xor_sync(0xffffffffu, l_lo, 2);
    l_hi += __shfl_xor_sync(0xffffffffu, l_hi, 1);
    l_hi += __shfl_xor_sync(0xffffffffu, l_hi, 2);
    float i0 = 1.0f / l_lo, i1 = 1.0f / l_hi;

    size_t base0 = ((size_t)b * Nn + qr) * Ci;
    size_t base1 = base0 + 8 * Ci;
#pragma unroll
    for (int nb = 0; nb < 16; nb++) {
        float v0 = O[nb * 4 + 0] * i0, v1 = O[nb * 4 + 1] * i0;
        float v2 = O[nb * 4 + 2] * i1, v3 = O[nb * 4 + 3] * i1;
        __nv_bfloat16 h0, l0, h1, l1;
        split_bf16(v0, h0, l0); split_bf16(v1, h1, l1);
        *(uint32_t*)&d_o_h[base0 + nb * 8 + tig2] =
            (uint32_t)__bfloat16_as_ushort(h0) | ((uint32_t)__bfloat16_as_ushort(h1) << 16);
        *(uint32_t*)&d_o_l[base0 + nb * 8 + tig2] =
            (uint32_t)__bfloat16_as_ushort(l0) | ((uint32_t)__bfloat16_as_ushort(l1) << 16);
        split_bf16(v2, h0, l0); split_bf16(v3, h1, l1);
        *(uint32_t*)&d_o_h[base1 + nb * 8 + tig2] =
            (uint32_t)__bfloat16_as_ushort(h0) | ((uint32_t)__bfloat16_as_ushort(h1) << 16);
        *(uint32_t*)&d_o_l[base1 + nb * 8 + tig2] =
            (uint32_t)__bfloat16_as_ushort(l0) | ((uint32_t)__bfloat16_as_ushort(l1) << 16);
    }
}

// ---------------------------------------------------------------------------
// tensor-core W projection + fused BN stats, 2-stage cp.async pipelined.
// ---------------------------------------------------------------------------
#define WSTG 40960
#define WPROJ_SMEM 81920

__global__ __launch_bounds__(256, 2)
void wproj_mma_kernel(const __nv_bfloat16* __restrict__ w_h, const __nv_bfloat16* __restrict__ w_l,
                      const float* __restrict__ bias)
{
    extern __shared__ char dsm[];
    const uint32_t sb = smem_u32(dsm);

    const int b = blockIdx.z, cb0 = blockIdx.y << 7, n0 = blockIdx.x << 7;
    const int tid = threadIdx.x, w = tid >> 5, l = tid & 31;
    const int g = l >> 2, tig2 = (l & 3) * 2;

    const __nv_bfloat16* Bin_h = d_o_h + ((size_t)b * Nn + n0) * Ci;
    const __nv_bfloat16* Bin_l = d_o_l + ((size_t)b * Nn + n0) * Ci;

    const uint32_t lmoff = (uint32_t)((((l & 7) | ((l >> 4) << 3)) * 80) + ((l >> 3) & 1) * 16);

    {
        const int k0 = 0;
        uint32_t st = sb;
#pragma unroll
        for (int p = 0; p < 8; p++) {
            int f = tid + (p << 8);
            int buf = f >> 9, idx = f & 511;
            int row = idx >> 2, seg = idx & 3;
            const __nv_bfloat16* src =
                (buf == 0) ? w_h   + (size_t)(cb0 + row) * Ci + k0 + seg * 8 :
                (buf == 1) ? w_l   + (size_t)(cb0 + row) * Ci + k0 + seg * 8 :
                (buf == 2) ? Bin_h + (size_t)row * Ci + k0 + seg * 8 :
                             Bin_l + (size_t)row * Ci + k0 + seg * 8;
            CPA16(st + (uint32_t)(buf * 10240 + row * 80 + seg * 16), src);
        }
        CPC();
    }

    float acc[64];
#pragma unroll
    for (int i = 0; i < 64; i++) acc[i] = 0.f;

    for (int c = 0; c < 4; c++) {
        if (c < 3) {
            const int k0 = (c + 1) * 32;
            uint32_t st = sb + ((c + 1) & 1) * WSTG;
#pragma unroll
            for (int p = 0; p < 8; p++) {
                int f = tid + (p << 8);
                int buf = f >> 9, idx = f & 511;
                int row = idx >> 2, seg = idx & 3;
                const __nv_bfloat16* src =
                    (buf == 0) ? w_h   + (size_t)(cb0 + row) * Ci + k0 + seg * 8 :
                    (buf == 1) ? w_l   + (size_t)(cb0 + row) * Ci + k0 + seg * 8 :
                    (buf == 2) ? Bin_h + (size_t)row * Ci + k0 + seg * 8 :
                                 Bin_l + (size_t)row * Ci + k0 + seg * 8;
                CPA16(st + (uint32_t)(buf * 10240 + row * 80 + seg * 16), src);
            }
            CPC();
            CPW1();
        } else {
            CPW0();
        }
        __syncthreads();

        const uint32_t st = sb + (c & 1) * WSTG;
        const uint32_t sAh = st, sAl = st + 10240, sBh = st + 20480, sBl = st + 30720;

#pragma unroll
        for (int kc = 0; kc < 2; kc++) {
            uint32_t aH[4], aL[4];
            uint32_t abase = w * 16 * 80 + lmoff + kc * 32;
            LDSM4(aH[0], aH[2], aH[1], aH[3], sAh + abase);
            LDSM4(aL[0], aL[2], aL[1], aL[3], sAl + abase);
#pragma unroll
            for (int np = 0; np < 8; np++) {
                uint32_t bbase = np * 16 * 80 + lmoff + kc * 32;
                uint32_t h0, h1, h2, h3, e0, e1, e2, e3;
                LDSM4(h0, h1, h2, h3, sBh + bbase);
                LDSM4(e0, e1, e2, e3, sBl + bbase);
                MMA16816(acc + (np * 2 + 0) * 4, aH, h0, h1);
                MMA16816(acc + (np * 2 + 0) * 4, aL, h0, h1);
                MMA16816(acc + (np * 2 + 0) * 4, aH, e0, e1);
                MMA16816(acc + (np * 2 + 1) * 4, aH, h2, h3);
                MMA16816(acc + (np * 2 + 1) * 4, aL, h2, h3);
                MMA16816(acc + (np * 2 + 1) * 4, aH, e2, e3);
            }
        }
        __syncthreads();
    }

    const int c0 = cb0 + w * 16 + g;
    float bv0 = __ldg(&bias[c0]), bv1 = __ldg(&bias[c0 + 8]);
    float s0 = 0.f, q0 = 0.f, s1 = 0.f, q1 = 0.f;
#pragma unroll
    for (int j = 0; j < 16; j++) {
        int ncol = n0 + (j >> 1) * 16 + (j & 1) * 8 + tig2;
        float v0 = acc[j * 4 + 0] + bv0, v1 = acc[j * 4 + 1] + bv0;
        float v2 = acc[j * 4 + 2] + bv1, v3 = acc[j * 4 + 3] + bv1;
        s0 += v0 + v1; q0 += v0 * v0 + v1 * v1;
        s1 += v2 + v3; q1 += v2 * v2 + v3 * v3;
        *(float2*)&d_wy[((size_t)b * Cc + c0) * Nn + ncol]     = make_float2(v0, v1);
        *(float2*)&d_wy[((size_t)b * Cc + c0 + 8) * Nn + ncol] = make_float2(v2, v3);
    }
    s0 += __shfl_xor_sync(0xffffffffu, s0, 1); s0 += __shfl_xor_sync(0xffffffffu, s0, 2);
    q0 += __shfl_xor_sync(0xffffffffu, q0, 1); q0 += __shfl_xor_sync(0xffffffffu, q0, 2);
    s1 += __shfl_xor_sync(0xffffffffu, s1, 1); s1 += __shfl_xor_sync(0xffffffffu, s1, 2);
    q1 += __shfl_xor_sync(0xffffffffu, q1, 1); q1 += __shfl_xor_sync(0xffffffffu, q1, 2);
    if ((l & 3) == 0) {
        atomicAdd(&d_bnacc[c0], s0);          atomicAdd(&d_bnacc[Cc + c0], q0);
        atomicAdd(&d_bnacc[c0 + 8], s1);      atomicAdd(&d_bnacc[Cc + c0 + 8], q1);
    }
}

// ------- finalize: BN stats inline + affine + residual ---------------------
__global__ void finalize_kernel(const float* __restrict__ x,
                                const float* __restrict__ gamma,
                                const float* __restrict__ beta,
                                float* __restrict__ out)
{
    size_t i4 = (size_t)blockIdx.x * blockDim.x + threadIdx.x;
    size_t total4 = (size_t)Bn * Cc * Nn / 4;
    if (i4 >= total4) return;
    size_t i = i4 * 4;
    int c = (int)((i >> 12) & (Cc - 1));
    const float inv = 1.0f / (float)(Bn * Nn);
    float mean = __ldg(&d_bnacc[c]) * inv;
    float var = fmaxf(__ldg(&d_bnacc[Cc + c]) * inv - mean * mean, 0.f);
    float rstd = rsqrtf(var + 1e-5f);
    float ga = __ldg(&gamma[c]) * rstd;
    float be = __ldg(&beta[c]);
    float4 w  = *(const float4*)&d_wy[i];
    float4 xv = *(const float4*)&x[i];
    float4 o;
    o.x = (w.x - mean) * ga + be + xv.x;
    o.y = (w.y - mean) * ga + be + xv.y;
    o.z = (w.z - mean) * ga + be + xv.z;
    o.w = (w.w - mean) * ga + be + xv.w;
    *(float4*)&out[i] = o;
}

// ---------------------------------------------------------------------------
extern "C" void kernel_launch(void* const* d_in, const int* in_sizes, int n_in,
                              void* d_out, int out_size)
{
    const float* x       = (const float*)d_in[0];
    const float* y       = (const float*)d_in[1];
    const float* theta_w = (const float*)d_in[2];
    const float* theta_b = (const float*)d_in[3];
    const float* phi_w   = (const float*)d_in[4];
    const float* phi_b   = (const float*)d_in[5];
    const float* g_w     = (const float*)d_in[6];
    const float* g_b     = (const float*)d_in[7];
    const float* w_w     = (const float*)d_in[8];
    const float* w_b     = (const float*)d_in[9];
    const float* gamma   = (const float*)d_in[10];
    const float* beta    = (const float*)d_in[11];
    float* out = (float*)d_out;

    cudaFuncSetAttribute(attn_mma_kernel, cudaFuncAttributeMaxDynamicSharedMemorySize, ATT_SMEM);
    cudaFuncSetAttribute(conv_mma_kernel, cudaFuncAttributeMaxDynamicSharedMemorySize, CONV_SMEM);
    cudaFuncSetAttribute(conv2_mma_kernel, cudaFuncAttributeMaxDynamicSharedMemorySize, CONV2_SMEM);
    cudaFuncSetAttribute(wproj_mma_kernel, cudaFuncAttributeMaxDynamicSharedMemorySize, WPROJ_SMEM);

    __nv_bfloat16 *wh_p, *wl_p, *thh, *thl;
    float *bnacc_p;
    cudaGetSymbolAddress((void**)&wh_p, d_wh);
    cudaGetSymbolAddress((void**)&wl_p, d_wl);
    cudaGetSymbolAddress((void**)&thh, d_th_h);
    cudaGetSymbolAddress((void**)&thl, d_th_l);
    cudaGetSymbolAddress((void**)&bnacc_p, d_bnacc);

    cudaMemsetAsync(bnacc_p, 0, 2 * Cc * sizeof(float));

    split_w_kernel<<<512, 256>>>(theta_w, phi_w, g_w, w_w);

    dim3 gConv(Nn / 128, Bn);
    conv_mma_kernel<<<gConv, 256, CONV_SMEM>>>(x, wh_p, wl_p, theta_b, thh, thl);
    conv2_mma_kernel<<<gConv, 256, CONV2_SMEM>>>(y, wh_p + 32768, wl_p + 32768,
                                                 wh_p + 2 * 32768, wl_p + 2 * 32768,
                                                 phi_b, g_b);

    attn_mma_kernel<<<dim3(Nn / 128, Bn), 256, ATT_SMEM>>>();

    wproj_mma_kernel<<<dim3(Nn / 128, Cc / 128, Bn), 256, WPROJ_SMEM>>>(wh_p + 3 * 32768, wl_p + 3 * 32768, w_b);
    finalize_kernel<<<(Bn * Cc * Nn / 4 + 255) / 256, 256>>>(x, gamma, beta, out);
}

// round 17
// speedup vs baseline: 1.1300x; 1.0816x over previous
#include <cuda_runtime.h>
#include <cuda_bf16.h>
#include <cstdint>

#define Bn 8
#define Cc 256
#define Ci 128
#define Nn 4096   // 64*64
#define Mm 1024   // 32*32

// ---------------- scratch (static device allocations; no cudaMalloc) ------
__device__ __nv_bfloat16 d_wh  [4 * 32768];             // weight splits (theta,phi,g,w)
__device__ __nv_bfloat16 d_wl  [4 * 32768];
__device__ __nv_bfloat16 d_th_h[(size_t)Bn * Nn * Ci];  // theta hi [b][n][ci]
__device__ __nv_bfloat16 d_th_l[(size_t)Bn * Nn * Ci];
__device__ __nv_bfloat16 d_k_h [(size_t)Bn * Mm * Ci];  // K hi [b][m][ci]
__device__ __nv_bfloat16 d_k_l [(size_t)Bn * Mm * Ci];
__device__ __nv_bfloat16 d_v_h [(size_t)Bn * Mm * Ci];  // V hi [b][m][ci]
__device__ __nv_bfloat16 d_v_l [(size_t)Bn * Mm * Ci];
__device__ __nv_bfloat16 d_o_h [(size_t)Bn * Nn * Ci];  // attn out hi [b][n][ci]
__device__ __nv_bfloat16 d_o_l [(size_t)Bn * Nn * Ci];
__device__ float d_wy   [(size_t)Bn * Cc * Nn];         // [b][c][n]
__device__ float d_bnacc[2 * Cc];                       // BN partial sums (sum | sumsq)

__device__ __forceinline__ uint32_t smem_u32(const void* p) {
    uint32_t a;
    asm("{ .reg .u64 t; cvta.to.shared.u64 t, %1; cvt.u32.u64 %0, t; }" : "=r"(a) : "l"(p));
    return a;
}
__device__ __forceinline__ uint32_t pack_bf16x2(float lo, float hi) {
    __nv_bfloat16 a = __float2bfloat16(lo), b = __float2bfloat16(hi);
    return (uint32_t)__bfloat16_as_ushort(a) | ((uint32_t)__bfloat16_as_ushort(b) << 16);
}
__device__ __forceinline__ void split_bf16(float v, __nv_bfloat16& h, __nv_bfloat16& l) {
    h = __float2bfloat16(v);
    l = __float2bfloat16(v - __bfloat162float(h));
}

#define LDSM4(r0, r1, r2, r3, addr) \
    asm volatile("ldmatrix.sync.aligned.m8n8.x4.shared.b16 {%0,%1,%2,%3}, [%4];" \
        : "=r"(r0), "=r"(r1), "=r"(r2), "=r"(r3) : "r"(addr))
#define LDSM4T(r0, r1, r2, r3, addr) \
    asm volatile("ldmatrix.sync.aligned.m8n8.x4.trans.shared.b16 {%0,%1,%2,%3}, [%4];" \
        : "=r"(r0), "=r"(r1), "=r"(r2), "=r"(r3) : "r"(addr))

#define MMA16816(C, A, b0, b1) \
    asm volatile("mma.sync.aligned.m16n8k16.row.col.f32.bf16.bf16.f32 " \
        "{%0,%1,%2,%3}, {%4,%5,%6,%7}, {%8,%9}, {%0,%1,%2,%3};" \
        : "+f"((C)[0]), "+f"((C)[1]), "+f"((C)[2]), "+f"((C)[3]) \
        : "r"((A)[0]), "r"((A)[1]), "r"((A)[2]), "r"((A)[3]), "r"(b0), "r"(b1))

#define CPA16(dst, src) \
    asm volatile("cp.async.cg.shared.global [%0], [%1], 16;" :: "r"(dst), "l"(src))
#define CPC() asm volatile("cp.async.commit_group;" ::: "memory")
#define CPW0() asm volatile("cp.async.wait_group 0;" ::: "memory")
#define CPW1() asm volatile("cp.async.wait_group 1;" ::: "memory")

// ---------------------------------------------------------------------------
// split all 4 weight matrices into bf16 hi/lo (elementwise)
// ---------------------------------------------------------------------------
__global__ void split_w_kernel(const float* __restrict__ tw, const float* __restrict__ pw,
                               const float* __restrict__ gw, const float* __restrict__ ww)
{
    int idx = blockIdx.x * blockDim.x + threadIdx.x;
    int seg = idx >> 15, off = idx & 32767;
    const float* src = (seg == 0) ? tw : (seg == 1) ? pw : (seg == 2) ? gw : ww;
    float v = src[off];
    __nv_bfloat16 h, l;
    split_bf16(v, h, l);
    d_wh[idx] = h; d_wl[idx] = l;
}

// ---------------------------------------------------------------------------
// tensor-core conv1x1 (theta path), reads fp32 X [b][c][n] directly.
// ---------------------------------------------------------------------------
#define APITCH 132
#define CSTG 37376
#define CONV_SMEM 74752

__global__ __launch_bounds__(256, 2)
void conv_mma_kernel(const float* __restrict__ X,
                     const __nv_bfloat16* __restrict__ w_h, const __nv_bfloat16* __restrict__ w_l,
                     const float* __restrict__ bias,
                     __nv_bfloat16* __restrict__ out_h, __nv_bfloat16* __restrict__ out_l)
{
    extern __shared__ char dsm[];
    const uint32_t sb = smem_u32(dsm);

    const int b = blockIdx.y, n0 = blockIdx.x << 7;
    const int tid = threadIdx.x, w = tid >> 5, l = tid & 31;
    const int g = l >> 2, tig2 = (l & 3) * 2;

    const float* Ain = X + (size_t)b * Cc * Nn + n0;

    const uint32_t lmoff = (uint32_t)((((l & 7) | ((l >> 4) << 3)) * 80) + ((l >> 3) & 1) * 16);

    {
        uint32_t st = sb;
#pragma unroll
        for (int p = 0; p < 4; p++) {
            int f = tid + (p << 8);
            int row = f >> 5, seg = f & 31;
            CPA16(st + (uint32_t)(row * 528 + seg * 16), Ain + (size_t)row * Nn + seg * 4);
        }
#pragma unroll
        for (int p = 0; p < 4; p++) {
            int f = tid + (p << 8);
            int buf = f >> 9, idx = f & 511;
            int row = idx >> 2, seg = idx & 3;
            const __nv_bfloat16* src = (buf ? w_l : w_h) + (size_t)row * Cc + seg * 8;
            CPA16(st + (uint32_t)(16896 + buf * 10240 + row * 80 + seg * 16), src);
        }
        CPC();
    }

    float acc[64];
#pragma unroll
    for (int i = 0; i < 64; i++) acc[i] = 0.f;

    for (int c = 0; c < 8; c++) {
        if (c < 7) {
            const int k0 = (c + 1) * 32;
            uint32_t st = sb + ((c + 1) & 1) * CSTG;
#pragma unroll
            for (int p = 0; p < 4; p++) {
                int f = tid + (p << 8);
                int row = f >> 5, seg = f & 31;
                CPA16(st + (uint32_t)(row * 528 + seg * 16), Ain + (size_t)(k0 + row) * Nn + seg * 4);
            }
#pragma unroll
            for (int p = 0; p < 4; p++) {
                int f = tid + (p << 8);
                int buf = f >> 9, idx = f & 511;
                int row = idx >> 2, seg = idx & 3;
                const __nv_bfloat16* src = (buf ? w_l : w_h) + (size_t)row * Cc + k0 + seg * 8;
                CPA16(st + (uint32_t)(16896 + buf * 10240 + row * 80 + seg * 16), src);
            }
            CPC();
            CPW1();
        } else {
            CPW0();
        }
        __syncthreads();

        const float* As = (const float*)(dsm + (c & 1) * CSTG);
        const uint32_t st = sb + (c & 1) * CSTG;
        const uint32_t sBh = st + 16896, sBl = st + 27136;

#pragma unroll
        for (int kc = 0; kc < 2; kc++) {
            uint32_t aH[4], aL[4];
            const int kb = kc * 16 + tig2;
#pragma unroll
            for (int p = 0; p < 4; p++) {
                int k = kb + (p >> 1) * 8;
                int n = w * 16 + g + (p & 1) * 8;
                float v0 = As[k * APITCH + n];
                float v1 = As[(k + 1) * APITCH + n];
                __nv_bfloat16 h0, l0, h1, l1;
                split_bf16(v0, h0, l0); split_bf16(v1, h1, l1);
                aH[p] = (uint32_t)__bfloat16_as_ushort(h0) | ((uint32_t)__bfloat16_as_ushort(h1) << 16);
                aL[p] = (uint32_t)__bfloat16_as_ushort(l0) | ((uint32_t)__bfloat16_as_ushort(l1) << 16);
            }
#pragma unroll
            for (int np = 0; np < 8; np++) {
                uint32_t bbase = np * 16 * 80 + lmoff + kc * 32;
                uint32_t h0, h1, h2, h3, e0, e1, e2, e3;
                LDSM4(h0, h1, h2, h3, sBh + bbase);
                LDSM4(e0, e1, e2, e3, sBl + bbase);
                MMA16816(acc + (np * 2 + 0) * 4, aH, h0, h1);
                MMA16816(acc + (np * 2 + 0) * 4, aL, h0, h1);
                MMA16816(acc + (np * 2 + 0) * 4, aH, e0, e1);
                MMA16816(acc + (np * 2 + 1) * 4, aH, h2, h3);
                MMA16816(acc + (np * 2 + 1) * 4, aL, h2, h3);
                MMA16816(acc + (np * 2 + 1) * 4, aH, e2, e3);
            }
        }
        __syncthreads();
    }

    const int r0 = n0 + w * 16 + g;
#pragma unroll
    for (int j = 0; j < 16; j++) {
        int cb = (j >> 1) * 16 + (j & 1) * 8 + tig2;
        float b0 = __ldg(&bias[cb]), b1 = __ldg(&bias[cb + 1]);
        float v0 = acc[j * 4 + 0] + b0, v1 = acc[j * 4 + 1] + b1;
        float v2 = acc[j * 4 + 2] + b0, v3 = acc[j * 4 + 3] + b1;
        size_t p0 = ((size_t)b * Nn + r0) * Ci + cb;
        size_t p1 = p0 + 8 * Ci;
        __nv_bfloat16 h0, l0, h1, l1;
        split_bf16(v0, h0, l0); split_bf16(v1, h1, l1);
        *(uint32_t*)&out_h[p0] = (uint32_t)__bfloat16_as_ushort(h0) | ((uint32_t)__bfloat16_as_ushort(h1) << 16);
        *(uint32_t*)&out_l[p0] = (uint32_t)__bfloat16_as_ushort(l0) | ((uint32_t)__bfloat16_as_ushort(l1) << 16);
        split_bf16(v2, h0, l0); split_bf16(v3, h1, l1);
        *(uint32_t*)&out_h[p1] = (uint32_t)__bfloat16_as_ushort(h0) | ((uint32_t)__bfloat16_as_ushort(h1) << 16);
        *(uint32_t*)&out_l[p1] = (uint32_t)__bfloat16_as_ushort(l0) | ((uint32_t)__bfloat16_as_ushort(l1) << 16);
    }
}

// ---------------------------------------------------------------------------
// merged phi+g conv: reads y tile ONCE, runs both weight sets' MMAs.
// ---------------------------------------------------------------------------
#define C2STG 57856
#define CONV2_SMEM 115712

__global__ __launch_bounds__(256, 1)
void conv2_mma_kernel(const float* __restrict__ Y,
                      const __nv_bfloat16* __restrict__ pw_h, const __nv_bfloat16* __restrict__ pw_l,
                      const __nv_bfloat16* __restrict__ gw_h, const __nv_bfloat16* __restrict__ gw_l,
                      const float* __restrict__ pbias, const float* __restrict__ gbias)
{
    extern __shared__ char dsm[];
    const uint32_t sb = smem_u32(dsm);

    const int b = blockIdx.y, n0 = blockIdx.x << 7;
    const int tid = threadIdx.x, w = tid >> 5, l = tid & 31;
    const int g = l >> 2, tig2 = (l & 3) * 2;

    const float* Ain = Y + (size_t)b * Cc * Nn + n0;

    const uint32_t lmoff = (uint32_t)((((l & 7) | ((l >> 4) << 3)) * 80) + ((l >> 3) & 1) * 16);

    {
        uint32_t st = sb;
#pragma unroll
        for (int p = 0; p < 4; p++) {
            int f = tid + (p << 8);
            int row = f >> 5, seg = f & 31;
            CPA16(st + (uint32_t)(row * 528 + seg * 16), Ain + (size_t)row * Nn + seg * 4);
        }
#pragma unroll
        for (int p = 0; p < 8; p++) {
            int f = tid + (p << 8);
            int buf = f >> 9, idx = f & 511;
            int row = idx >> 2, seg = idx & 3;
            const __nv_bfloat16* src =
                (buf == 0) ? pw_h + (size_t)row * Cc + seg * 8 :
                (buf == 1) ? pw_l + (size_t)row * Cc + seg * 8 :
                (buf == 2) ? gw_h + (size_t)row * Cc + seg * 8 :
                             gw_l + (size_t)row * Cc + seg * 8;
            CPA16(st + (uint32_t)(16896 + buf * 10240 + row * 80 + seg * 16), src);
        }
        CPC();
    }

    float accP[64], accG[64];
#pragma unroll
    for (int i = 0; i < 64; i++) { accP[i] = 0.f; accG[i] = 0.f; }

    for (int c = 0; c < 8; c++) {
        if (c < 7) {
            const int k0 = (c + 1) * 32;
            uint32_t st = sb + ((c + 1) & 1) * C2STG;
#pragma unroll
            for (int p = 0; p < 4; p++) {
                int f = tid + (p << 8);
                int row = f >> 5, seg = f & 31;
                CPA16(st + (uint32_t)(row * 528 + seg * 16), Ain + (size_t)(k0 + row) * Nn + seg * 4);
            }
#pragma unroll
            for (int p = 0; p < 8; p++) {
                int f = tid + (p << 8);
                int buf = f >> 9, idx = f & 511;
                int row = idx >> 2, seg = idx & 3;
                const __nv_bfloat16* src =
                    (buf == 0) ? pw_h + (size_t)row * Cc + k0 + seg * 8 :
                    (buf == 1) ? pw_l + (size_t)row * Cc + k0 + seg * 8 :
                    (buf == 2) ? gw_h + (size_t)row * Cc + k0 + seg * 8 :
                                 gw_l + (size_t)row * Cc + k0 + seg * 8;
                CPA16(st + (uint32_t)(16896 + buf * 10240 + row * 80 + seg * 16), src);
            }
            CPC();
            CPW1();
        } else {
            CPW0();
        }
        __syncthreads();

        const float* As = (const float*)(dsm + (c & 1) * C2STG);
        const uint32_t st = sb + (c & 1) * C2STG;
        const uint32_t sPh = st + 16896, sPl = st + 27136;
        const uint32_t sGh = st + 37376, sGl = st + 47616;

#pragma unroll
        for (int kc = 0; kc < 2; kc++) {
            uint32_t aH[4], aL[4];
            const int kb = kc * 16 + tig2;
#pragma unroll
            for (int p = 0; p < 4; p++) {
                int k = kb + (p >> 1) * 8;
                int n = w * 16 + g + (p & 1) * 8;
                float v0 = As[k * APITCH + n];
                float v1 = As[(k + 1) * APITCH + n];
                __nv_bfloat16 h0, l0, h1, l1;
                split_bf16(v0, h0, l0); split_bf16(v1, h1, l1);
                aH[p] = (uint32_t)__bfloat16_as_ushort(h0) | ((uint32_t)__bfloat16_as_ushort(h1) << 16);
                aL[p] = (uint32_t)__bfloat16_as_ushort(l0) | ((uint32_t)__bfloat16_as_ushort(l1) << 16);
            }
#pragma unroll
            for (int np = 0; np < 8; np++) {
                uint32_t bbase = np * 16 * 80 + lmoff + kc * 32;
                uint32_t h0, h1, h2, h3, e0, e1, e2, e3;
                LDSM4(h0, h1, h2, h3, sPh + bbase);
                LDSM4(e0, e1, e2, e3, sPl + bbase);
                MMA16816(accP + (np * 2 + 0) * 4, aH, h0, h1);
                MMA16816(accP + (np * 2 + 0) * 4, aL, h0, h1);
                MMA16816(accP + (np * 2 + 0) * 4, aH, e0, e1);
                MMA16816(accP + (np * 2 + 1) * 4, aH, h2, h3);
                MMA16816(accP + (np * 2 + 1) * 4, aL, h2, h3);
                MMA16816(accP + (np * 2 + 1) * 4, aH, e2, e3);
                LDSM4(h0, h1, h2, h3, sGh + bbase);
                LDSM4(e0, e1, e2, e3, sGl + bbase);
                MMA16816(accG + (np * 2 + 0) * 4, aH, h0, h1);
                MMA16816(accG + (np * 2 + 0) * 4, aL, h0, h1);
                MMA16816(accG + (np * 2 + 0) * 4, aH, e0, e1);
                MMA16816(accG + (np * 2 + 1) * 4, aH, h2, h3);
                MMA16816(accG + (np * 2 + 1) * 4, aL, h2, h3);
                MMA16816(accG + (np * 2 + 1) * 4, aH, e2, e3);
            }
        }
        __syncthreads();
    }

    float* pb = (float*)dsm;   // [128][132]
    const int r0 = w * 16 + g;
    const int m0 = blockIdx.x << 5;

#pragma unroll
    for (int pass = 0; pass < 2; pass++) {
        const float* acc = pass ? accG : accP;
        const float* bias = pass ? gbias : pbias;
        __nv_bfloat16* oh = pass ? d_v_h : d_k_h;
        __nv_bfloat16* ol = pass ? d_v_l : d_k_l;
#pragma unroll
        for (int j = 0; j < 16; j++) {
            int cb = (j >> 1) * 16 + (j & 1) * 8 + tig2;
            float b0 = __ldg(&bias[cb]), b1 = __ldg(&bias[cb + 1]);
            pb[r0 * 132 + cb]           = acc[j * 4 + 0] + b0;
            pb[r0 * 132 + cb + 1]       = acc[j * 4 + 1] + b1;
            pb[(r0 + 8) * 132 + cb]     = acc[j * 4 + 2] + b0;
            pb[(r0 + 8) * 132 + cb + 1] = acc[j * 4 + 3] + b1;
        }
        __syncthreads();
#pragma unroll
        for (int rep = 0; rep < 16; rep++) {
            int idx = tid + rep * 256;
            int pj = idx >> 7, ci = idx & 127;
            int rA = pj * 2;
            float v = fmaxf(fmaxf(pb[rA * 132 + ci],        pb[(rA + 1) * 132 + ci]),
                            fmaxf(pb[(rA + 64) * 132 + ci], pb[(rA + 65) * 132 + ci]));
            __nv_bfloat16 h, lo;
            split_bf16(v, h, lo);
            size_t o = ((size_t)b * Mm + m0 + pj) * Ci + ci;
            oh[o] = h; ol[o] = lo;
        }
        __syncthreads();
    }
}

// ---------------------------------------------------------------------------
// mma.sync attention — fused per-m-chunk S->softmax->PV; K double-buffered,
// V single-buffered with half-tile prefetch. CTA: 8 warps x 16 query rows.
// smem: K hi/lo x2 stages + V hi/lo = 6 x 34816 = 208896 B, 1 CTA/SM.
// ---------------------------------------------------------------------------
#define TPAD 272
#define TILE_BYTES (128 * TPAD)            // 34816
#define ATT_SMEM (6 * TILE_BYTES)          // 208896
#define EXP_SHIFT 40.0f

__device__ __forceinline__ void load_tile_async(uint32_t dst, const __nv_bfloat16* src)
{
    for (int f = threadIdx.x; f < 2048; f += 256) {
        int row = f >> 4, seg = f & 15;
        CPA16(dst + (uint32_t)(row * TPAD + seg * 16), src + (size_t)row * Ci + seg * 8);
    }
}
// rows [r0, r0+64)
__device__ __forceinline__ void load_half_async(uint32_t dst, const __nv_bfloat16* src, int r0)
{
    for (int f = threadIdx.x; f < 1024; f += 256) {
        int row = r0 + (f >> 4), seg = f & 15;
        CPA16(dst + (uint32_t)(row * TPAD + seg * 16), src + (size_t)row * Ci + seg * 8);
    }
}

__global__ __launch_bounds__(256, 1) void attn_mma_kernel()
{
    extern __shared__ char smem[];
    const uint32_t sb = smem_u32(smem);
    const uint32_t sK0h = sb,                  sK0l = sb + TILE_BYTES;
    const uint32_t sK1h = sb + 2 * TILE_BYTES, sK1l = sb + 3 * TILE_BYTES;
    const uint32_t sVh  = sb + 4 * TILE_BYTES, sVl  = sb + 5 * TILE_BYTES;

    const int b = blockIdx.y, n0 = blockIdx.x << 7;
    const int tid = threadIdx.x, w = tid >> 5, l = tid & 31;
    const int g = l >> 2, tig2 = (l & 3) * 2;
    const int qr = n0 + w * 16 + g;

    const __nv_bfloat16* Kh = d_k_h + (size_t)b * Mm * Ci;
    const __nv_bfloat16* Kl = d_k_l + (size_t)b * Mm * Ci;
    const __nv_bfloat16* Vh = d_v_h + (size_t)b * Mm * Ci;
    const __nv_bfloat16* Vl = d_v_l + (size_t)b * Mm * Ci;

    // prologue: commits ordered to match steady state: K0 | Vlow0 | Vhigh0
    load_tile_async(sK0h, Kh); load_tile_async(sK0l, Kl); CPC();
    load_half_async(sVh, Vh, 0);  load_half_async(sVl, Vl, 0);  CPC();
    load_half_async(sVh, Vh, 64); load_half_async(sVl, Vl, 64); CPC();

    // ---- persistent Q fragments (hi/lo) ----
    uint32_t qh[32], ql[32];
    {
        const __nv_bfloat16* q0 = d_th_h + ((size_t)b * Nn + qr) * Ci;
        const __nv_bfloat16* q1 = q0 + 8 * Ci;
        const __nv_bfloat16* p0 = d_th_l + ((size_t)b * Nn + qr) * Ci;
        const __nv_bfloat16* p1 = p0 + 8 * Ci;
#pragma unroll
        for (int kc = 0; kc < 8; kc++) {
            int c0 = kc * 16 + tig2;
            qh[kc * 4 + 0] = *(const uint32_t*)(q0 + c0);
            qh[kc * 4 + 1] = *(const uint32_t*)(q1 + c0);
            qh[kc * 4 + 2] = *(const uint32_t*)(q0 + c0 + 8);
            qh[kc * 4 + 3] = *(const uint32_t*)(q1 + c0 + 8);
            ql[kc * 4 + 0] = *(const uint32_t*)(p0 + c0);
            ql[kc * 4 + 1] = *(const uint32_t*)(p1 + c0);
            ql[kc * 4 + 2] = *(const uint32_t*)(p0 + c0 + 8);
            ql[kc * 4 + 3] = *(const uint32_t*)(p1 + c0 + 8);
        }
    }

    const uint32_t lmoff  = (uint32_t)(((l & 7) | ((l >> 4) << 3)) * TPAD + ((l >> 3) & 1) * 16);
    const uint32_t lmoffV = (uint32_t)(((l & 7) | (((l >> 3) & 1) << 3)) * TPAD + (l >> 4) * 16);

    float O[64];
#pragma unroll
    for (int i = 0; i < 64; i++) O[i] = 0.f;
    float l_lo = 0.f, l_hi = 0.f;

    for (int it = 0; it < 8; it++) {
        CPW1();            // K(it) + Vlow(it) done (Vhigh(it) may be in flight)
        __syncthreads();

        const uint32_t kch = (it & 1) ? sK1h : sK0h;
        const uint32_t kcl = (it & 1) ? sK1l : sK0l;

        if (it < 7) {      // prefetch K(it+1) into the other K buffer
            const __nv_bfloat16* nKh = Kh + (size_t)(it + 1) * 128 * Ci;
            const __nv_bfloat16* nKl = Kl + (size_t)(it + 1) * 128 * Ci;
            uint32_t dsth = (it & 1) ? sK0h : sK1h;
            uint32_t dstl = (it & 1) ? sK0l : sK1l;
            load_tile_async(dsth, nKh); load_tile_async(dstl, nKl); CPC();
        }

#pragma unroll
        for (int np = 0; np < 8; np++) {
            if (np == 4) {
                CPW1();            // Vhigh(it) done (K(it+1) may remain in flight)
                __syncthreads();   // all warps finished reading V rows 0-63
                if (it < 7) {
                    load_half_async(sVh, Vh + (size_t)(it + 1) * 128 * Ci, 0);
                    load_half_async(sVl, Vl + (size_t)(it + 1) * 128 * Ci, 0);
                    CPC();
                }
            }
            // ---- S chunk: 16 keys, split accumulators (even/odd kc) ----
            float Sa[8], Sb[8];
#pragma unroll
            for (int i = 0; i < 8; i++) { Sa[i] = 0.f; Sb[i] = 0.f; }
            uint32_t kb  = kch + np * 16 * TPAD + lmoff;
            uint32_t kb2 = kcl + np * 16 * TPAD + lmoff;
#pragma unroll
            for (int kc = 0; kc < 8; kc++) {
                float* D = (kc & 1) ? Sb : Sa;
                uint32_t h0, h1, h2, h3, e0, e1, e2, e3;
                LDSM4(h0, h1, h2, h3, kb + kc * 32);
                LDSM4(e0, e1, e2, e3, kb2 + kc * 32);
                MMA16816(D,     qh + kc * 4, h0, h1);
                MMA16816(D,     ql + kc * 4, h0, h1);
                MMA16816(D,     qh + kc * 4, e0, e1);
                MMA16816(D + 4, qh + kc * 4, h2, h3);
                MMA16816(D + 4, ql + kc * 4, h2, h3);
                MMA16816(D + 4, qh + kc * 4, e2, e3);
            }
            // ---- softmax numerator for this chunk ----
            float p[8];
#pragma unroll
            for (int i = 0; i < 8; i++) p[i] = __expf((Sa[i] + Sb[i]) - EXP_SHIFT);
            l_lo += (p[0] + p[1]) + (p[4] + p[5]);
            l_hi += (p[2] + p[3]) + (p[6] + p[7]);
            uint32_t Pc[8];
            {
                float hf[8], lf[8];
#pragma unroll
                for (int i = 0; i < 8; i++) {
                    __nv_bfloat16 h = __float2bfloat16(p[i]);
                    hf[i] = __bfloat162float(h);
                    lf[i] = p[i] - hf[i];
                }
                Pc[0] = pack_bf16x2(hf[0], hf[1]);
                Pc[1] = pack_bf16x2(hf[2], hf[3]);
                Pc[2] = pack_bf16x2(hf[4], hf[5]);
                Pc[3] = pack_bf16x2(hf[6], hf[7]);
                Pc[4] = pack_bf16x2(lf[0], lf[1]);
                Pc[5] = pack_bf16x2(lf[2], lf[3]);
                Pc[6] = pack_bf16x2(lf[4], lf[5]);
                Pc[7] = pack_bf16x2(lf[6], lf[7]);
            }
            // ---- PV for this m-chunk: V rows np*16..np*16+15 ----
#pragma unroll
            for (int np2 = 0; np2 < 8; np2++) {
                uint32_t vb  = sVh + np * 16 * TPAD + np2 * 32 + lmoffV;
                uint32_t vb2 = sVl + np * 16 * TPAD + np2 * 32 + lmoffV;
                uint32_t h0, h1, h2, h3, e0, e1, e2, e3;
                LDSM4T(h0, h1, h2, h3, vb);
                LDSM4T(e0, e1, e2, e3, vb2);
                MMA16816(O + np2 * 8,     Pc,     h0, h1);
                MMA16816(O + np2 * 8,     Pc + 4, h0, h1);
                MMA16816(O + np2 * 8,     Pc,     e0, e1);
                MMA16816(O + np2 * 8 + 4, Pc,     h2, h3);
                MMA16816(O + np2 * 8 + 4, Pc + 4, h2, h3);
                MMA16816(O + np2 * 8 + 4, Pc,     e2, e3);
            }
        }

        __syncthreads();   // all warps finished V rows 64-127 + K(it) reads
        if (it < 7) {
            load_half_async(sVh, Vh + (size_t)(it + 1) * 128 * Ci, 64);
            load_half_async(sVl, Vl + (size_t)(it + 1) * 128 * Ci, 64);
            CPC();
        }
    }

    l_lo += __shfl_xor_sync(0xffffffffu, l_lo, 1);
    l_lo += __shfl_xor_sync(0xffffffffu, l_lo, 2);
    l_hi += __shfl_xor_sync(0xffffffffu, l_hi, 1);
    l_hi += __shfl_xor_sync(0xffffffffu, l_hi, 2);
    float i0 = 1.0f / l_lo, i1 = 1.0f / l_hi;

    size_t base0 = ((size_t)b * Nn + qr) * Ci;
    size_t base1 = base0 + 8 * Ci;
#pragma unroll
    for (int nb = 0; nb < 16; nb++) {
        float v0 = O[nb * 4 + 0] * i0, v1 = O[nb * 4 + 1] * i0;
        float v2 = O[nb * 4 + 2] * i1, v3 = O[nb * 4 + 3] * i1;
        __nv_bfloat16 h0, l0, h1, l1;
        split_bf16(v0, h0, l0); split_bf16(v1, h1, l1);
        *(uint32_t*)&d_o_h[base0 + nb * 8 + tig2] =
            (uint32_t)__bfloat16_as_ushort(h0) | ((uint32_t)__bfloat16_as_ushort(h1) << 16);
        *(uint32_t*)&d_o_l[base0 + nb * 8 + tig2] =
            (uint32_t)__bfloat16_as_ushort(l0) | ((uint32_t)__bfloat16_as_ushort(l1) << 16);
        split_bf16(v2, h0, l0); split_bf16(v3, h1, l1);
        *(uint32_t*)&d_o_h[base1 + nb * 8 + tig2] =
            (uint32_t)__bfloat16_as_ushort(h0) | ((uint32_t)__bfloat16_as_ushort(h1) << 16);
        *(uint32_t*)&d_o_l[base1 + nb * 8 + tig2] =
            (uint32_t)__bfloat16_as_ushort(l0) | ((uint32_t)__bfloat16_as_ushort(l1) << 16);
    }
}

// ---------------------------------------------------------------------------
// tensor-core W projection + fused BN stats, 2-stage cp.async pipelined.
// ---------------------------------------------------------------------------
#define WSTG 40960
#define WPROJ_SMEM 81920

__global__ __launch_bounds__(256, 2)
void wproj_mma_kernel(const __nv_bfloat16* __restrict__ w_h, const __nv_bfloat16* __restrict__ w_l,
                      const float* __restrict__ bias)
{
    extern __shared__ char dsm[];
    const uint32_t sb = smem_u32(dsm);

    const int b = blockIdx.z, cb0 = blockIdx.y << 7, n0 = blockIdx.x << 7;
    const int tid = threadIdx.x, w = tid >> 5, l = tid & 31;
    const int g = l >> 2, tig2 = (l & 3) * 2;

    const __nv_bfloat16* Bin_h = d_o_h + ((size_t)b * Nn + n0) * Ci;
    const __nv_bfloat16* Bin_l = d_o_l + ((size_t)b * Nn + n0) * Ci;

    const uint32_t lmoff = (uint32_t)((((l & 7) | ((l >> 4) << 3)) * 80) + ((l >> 3) & 1) * 16);

    {
        const int k0 = 0;
        uint32_t st = sb;
#pragma unroll
        for (int p = 0; p < 8; p++) {
            int f = tid + (p << 8);
            int buf = f >> 9, idx = f & 511;
            int row = idx >> 2, seg = idx & 3;
            const __nv_bfloat16* src =
                (buf == 0) ? w_h   + (size_t)(cb0 + row) * Ci + k0 + seg * 8 :
                (buf == 1) ? w_l   + (size_t)(cb0 + row) * Ci + k0 + seg * 8 :
                (buf == 2) ? Bin_h + (size_t)row * Ci + k0 + seg * 8 :
                             Bin_l + (size_t)row * Ci + k0 + seg * 8;
            CPA16(st + (uint32_t)(buf * 10240 + row * 80 + seg * 16), src);
        }
        CPC();
    }

    float acc[64];
#pragma unroll
    for (int i = 0; i < 64; i++) acc[i] = 0.f;

    for (int c = 0; c < 4; c++) {
        if (c < 3) {
            const int k0 = (c + 1) * 32;
            uint32_t st = sb + ((c + 1) & 1) * WSTG;
#pragma unroll
            for (int p = 0; p < 8; p++) {
                int f = tid + (p << 8);
                int buf = f >> 9, idx = f & 511;
                int row = idx >> 2, seg = idx & 3;
                const __nv_bfloat16* src =
                    (buf == 0) ? w_h   + (size_t)(cb0 + row) * Ci + k0 + seg * 8 :
                    (buf == 1) ? w_l   + (size_t)(cb0 + row) * Ci + k0 + seg * 8 :
                    (buf == 2) ? Bin_h + (size_t)row * Ci + k0 + seg * 8 :
                                 Bin_l + (size_t)row * Ci + k0 + seg * 8;
                CPA16(st + (uint32_t)(buf * 10240 + row * 80 + seg * 16), src);
            }
            CPC();
            CPW1();
        } else {
            CPW0();
        }
        __syncthreads();

        const uint32_t st = sb + (c & 1) * WSTG;
        const uint32_t sAh = st, sAl = st + 10240, sBh = st + 20480, sBl = st + 30720;

#pragma unroll
        for (int kc = 0; kc < 2; kc++) {
            uint32_t aH[4], aL[4];
            uint32_t abase = w * 16 * 80 + lmoff + kc * 32;
            LDSM4(aH[0], aH[2], aH[1], aH[3], sAh + abase);
            LDSM4(aL[0], aL[2], aL[1], aL[3], sAl + abase);
#pragma unroll
            for (int np = 0; np < 8; np++) {
                uint32_t bbase = np * 16 * 80 + lmoff + kc * 32;
                uint32_t h0, h1, h2, h3, e0, e1, e2, e3;
                LDSM4(h0, h1, h2, h3, sBh + bbase);
                LDSM4(e0, e1, e2, e3, sBl + bbase);
                MMA16816(acc + (np * 2 + 0) * 4, aH, h0, h1);
                MMA16816(acc + (np * 2 + 0) * 4, aL, h0, h1);
                MMA16816(acc + (np * 2 + 0) * 4, aH, e0, e1);
                MMA16816(acc + (np * 2 + 1) * 4, aH, h2, h3);
                MMA16816(acc + (np * 2 + 1) * 4, aL, h2, h3);
                MMA16816(acc + (np * 2 + 1) * 4, aH, e2, e3);
            }
        }
        __syncthreads();
    }

    const int c0 = cb0 + w * 16 + g;
    float bv0 = __ldg(&bias[c0]), bv1 = __ldg(&bias[c0 + 8]);
    float s0 = 0.f, q0 = 0.f, s1 = 0.f, q1 = 0.f;
#pragma unroll
    for (int j = 0; j < 16; j++) {
        int ncol = n0 + (j >> 1) * 16 + (j & 1) * 8 + tig2;
        float v0 = acc[j * 4 + 0] + bv0, v1 = acc[j * 4 + 1] + bv0;
        float v2 = acc[j * 4 + 2] + bv1, v3 = acc[j * 4 + 3] + bv1;
        s0 += v0 + v1; q0 += v0 * v0 + v1 * v1;
        s1 += v2 + v3; q1 += v2 * v2 + v3 * v3;
        *(float2*)&d_wy[((size_t)b * Cc + c0) * Nn + ncol]     = make_float2(v0, v1);
        *(float2*)&d_wy[((size_t)b * Cc + c0 + 8) * Nn + ncol] = make_float2(v2, v3);
    }
    s0 += __shfl_xor_sync(0xffffffffu, s0, 1); s0 += __shfl_xor_sync(0xffffffffu, s0, 2);
    q0 += __shfl_xor_sync(0xffffffffu, q0, 1); q0 += __shfl_xor_sync(0xffffffffu, q0, 2);
    s1 += __shfl_xor_sync(0xffffffffu, s1, 1); s1 += __shfl_xor_sync(0xffffffffu, s1, 2);
    q1 += __shfl_xor_sync(0xffffffffu, q1, 1); q1 += __shfl_xor_sync(0xffffffffu, q1, 2);
    if ((l & 3) == 0) {
        atomicAdd(&d_bnacc[c0], s0);          atomicAdd(&d_bnacc[Cc + c0], q0);
        atomicAdd(&d_bnacc[c0 + 8], s1);      atomicAdd(&d_bnacc[Cc + c0 + 8], q1);
    }
}

// ------- finalize: BN stats inline + affine + residual ---------------------
__global__ void finalize_kernel(const float* __restrict__ x,
                                const float* __restrict__ gamma,
                                const float* __restrict__ beta,
                                float* __restrict__ out)
{
    size_t i4 = (size_t)blockIdx.x * blockDim.x + threadIdx.x;
    size_t total4 = (size_t)Bn * Cc * Nn / 4;
    if (i4 >= total4) return;
    size_t i = i4 * 4;
    int c = (int)((i >> 12) & (Cc - 1));
    const float inv = 1.0f / (float)(Bn * Nn);
    float mean = __ldg(&d_bnacc[c]) * inv;
    float var = fmaxf(__ldg(&d_bnacc[Cc + c]) * inv - mean * mean, 0.f);
    float rstd = rsqrtf(var + 1e-5f);
    float ga = __ldg(&gamma[c]) * rstd;
    float be = __ldg(&beta[c]);
    float4 w  = *(const float4*)&d_wy[i];
    float4 xv = *(const float4*)&x[i];
    float4 o;
    o.x = (w.x - mean) * ga + be + xv.x;
    o.y = (w.y - mean) * ga + be + xv.y;
    o.z = (w.z - mean) * ga + be + xv.z;
    o.w = (w.w - mean) * ga + be + xv.w;
    *(float4*)&out[i] = o;
}

// ---------------------------------------------------------------------------
extern "C" void kernel_launch(void* const* d_in, const int* in_sizes, int n_in,
                              void* d_out, int out_size)
{
    const float* x       = (const float*)d_in[0];
    const float* y       = (const float*)d_in[1];
    const float* theta_w = (const float*)d_in[2];
    const float* theta_b = (const float*)d_in[3];
    const float* phi_w   = (const float*)d_in[4];
    const float* phi_b   = (const float*)d_in[5];
    const float* g_w     = (const float*)d_in[6];
    const float* g_b     = (const float*)d_in[7];
    const float* w_w     = (const float*)d_in[8];
    const float* w_b     = (const float*)d_in[9];
    const float* gamma   = (const float*)d_in[10];
    const float* beta    = (const float*)d_in[11];
    float* out = (float*)d_out;

    cudaFuncSetAttribute(attn_mma_kernel, cudaFuncAttributeMaxDynamicSharedMemorySize, ATT_SMEM);
    cudaFuncSetAttribute(conv_mma_kernel, cudaFuncAttributeMaxDynamicSharedMemorySize, CONV_SMEM);
    cudaFuncSetAttribute(conv2_mma_kernel, cudaFuncAttributeMaxDynamicSharedMemorySize, CONV2_SMEM);
    cudaFuncSetAttribute(wproj_mma_kernel, cudaFuncAttributeMaxDynamicSharedMemorySize, WPROJ_SMEM);

    __nv_bfloat16 *wh_p, *wl_p, *thh, *thl;
    float *bnacc_p;
    cudaGetSymbolAddress((void**)&wh_p, d_wh);
    cudaGetSymbolAddress((void**)&wl_p, d_wl);
    cudaGetSymbolAddress((void**)&thh, d_th_h);
    cudaGetSymbolAddress((void**)&thl, d_th_l);
    cudaGetSymbolAddress((void**)&bnacc_p, d_bnacc);

    cudaMemsetAsync(bnacc_p, 0, 2 * Cc * sizeof(float));

    split_w_kernel<<<512, 256>>>(theta_w, phi_w, g_w, w_w);

    dim3 gConv(Nn / 128, Bn);
    conv_mma_kernel<<<gConv, 256, CONV_SMEM>>>(x, wh_p, wl_p, theta_b, thh, thl);
    conv2_mma_kernel<<<gConv, 256, CONV2_SMEM>>>(y, wh_p + 32768, wl_p + 32768,
                                                 wh_p + 2 * 32768, wl_p + 2 * 32768,
                                                 phi_b, g_b);

    attn_mma_kernel<<<dim3(Nn / 128, Bn), 256, ATT_SMEM>>>();

    wproj_mma_kernel<<<dim3(Nn / 128, Cc / 128, Bn), 256, WPROJ_SMEM>>>(wh_p + 3 * 32768, wl_p + 3 * 32768, w_b);
    finalize_kernel<<<(Bn * Cc * Nn / 4 + 255) / 256, 256>>>(x, gamma, beta, out);
}